// round 10
// baseline (speedup 1.0000x reference)
#include <cuda_runtime.h>
#include <cuda_fp16.h>
#include <stdint.h>
#include <math.h>
#include <float.h>

// ---------------- problem constants ----------------
#define BB    2
#define TT    2048
#define CCH   2048
#define HH    16
#define HDD   128
#define LORA_ 512
#define RDIM  64
#define NDIM  64
#define MTOT  (BB*TT)        /* 4096 */
#define CKVW  (LORA_+RDIM)   /* 576  */
#define KVW   (HH*NDIM)      /* 1024 */
#define NAPAD 640

// ---------------- fp16 split (hi/lo) buffers ----------------
__device__ __align__(128) __half g_xh [(size_t)MTOT*CCH],  g_xl [(size_t)MTOT*CCH];
__device__ __align__(128) __half g_wqh[(size_t)2048*2048], g_wql[(size_t)2048*2048];
__device__ __align__(128) __half g_wah[(size_t)NAPAD*2048],g_wal[(size_t)NAPAD*2048];
__device__ __align__(128) __half g_wbh[(size_t)1024*512],  g_wbl[(size_t)1024*512];
__device__ __align__(128) __half g_woh[(size_t)2048*1024], g_wol[(size_t)2048*1024];
__device__ __align__(128) __half g_a4h[(size_t)MTOT*512],  g_a4l[(size_t)MTOT*512];
__device__ __align__(128) __half g_a6h[(size_t)MTOT*1024], g_a6l[(size_t)MTOT*1024];
// attention operands [bh][t][d]; V == K[:, 0:64]
__device__ __align__(128) __half g_Qh[(size_t)BB*HH*TT*128], g_Ql[(size_t)BB*HH*TT*128];
__device__ __align__(128) __half g_Kh[(size_t)BB*HH*TT*128], g_Kl[(size_t)BB*HH*TT*128];

// =====================================================================
// PTX helpers (baseline sm_80+ — compile at compute_103)
// =====================================================================
__device__ __forceinline__ uint32_t smem_u32(const void* p) {
    uint32_t a;
    asm("{ .reg .u64 t; cvta.to.shared.u64 t, %1; cvt.u32.u64 %0, t; }" : "=r"(a) : "l"(p));
    return a;
}
#define CP_ASYNC16(dst, src) \
    asm volatile("cp.async.cg.shared.global [%0], [%1], 16;" :: "r"(dst), "l"(src))
#define CP_COMMIT() asm volatile("cp.async.commit_group;" ::: "memory")
#define CP_WAIT(n)  asm volatile("cp.async.wait_group %0;" :: "n"(n) : "memory")

#define LDSM4(R, addr) \
    asm volatile("ldmatrix.sync.aligned.m8n8.x4.shared.b16 {%0,%1,%2,%3}, [%4];" \
        : "=r"((R)[0]), "=r"((R)[1]), "=r"((R)[2]), "=r"((R)[3]) : "r"(addr))
#define LDSM4T(R, addr) \
    asm volatile("ldmatrix.sync.aligned.m8n8.x4.trans.shared.b16 {%0,%1,%2,%3}, [%4];" \
        : "=r"((R)[0]), "=r"((R)[1]), "=r"((R)[2]), "=r"((R)[3]) : "r"(addr))

#define MMA16816(D, A, B0, B1) \
    asm volatile("mma.sync.aligned.m16n8k16.row.col.f32.f16.f16.f32 " \
        "{%0,%1,%2,%3}, {%4,%5,%6,%7}, {%8,%9}, {%0,%1,%2,%3};" \
        : "+f"((D)[0]), "+f"((D)[1]), "+f"((D)[2]), "+f"((D)[3]) \
        : "r"((A)[0]), "r"((A)[1]), "r"((A)[2]), "r"((A)[3]), "r"(B0), "r"(B1))

__device__ __forceinline__ uint32_t h2u(__half2 v) { return *(uint32_t*)&v; }

// hi/lo split store of a (v0,v1) pair
__device__ __forceinline__ void sstore2(__half* __restrict__ oh, __half* __restrict__ ol,
                                        size_t idx, float v0, float v1)
{
    __half h0 = __float2half_rn(v0), h1 = __float2half_rn(v1);
    *(__half2*)(oh + idx) = __halves2half2(h0, h1);
    *(__half2*)(ol + idx) = __halves2half2(__float2half_rn(v0 - __half2float(h0)),
                                           __float2half_rn(v1 - __half2float(h1)));
}

// RoPE on one (even,odd) pair; i = freq index, t = position
__device__ __forceinline__ void rope2(float& v0, float& v1, int t, int i)
{
    float freq = powf(100000.0f, -(float)i * (1.0f/32.0f));
    float sn, cs; sincosf((float)t * freq, &sn, &cs);
    float a = v0*cs - v1*sn;
    float b = v0*sn + v1*cs;
    v0 = a; v1 = b;
}

// =====================================================================
// hi/lo split conversions (prep)
// =====================================================================
__global__ __launch_bounds__(256)
void convert_rows(const float* __restrict__ in, int ld, long total, int cols,
                  __half* __restrict__ oh, __half* __restrict__ ol)
{
    long i = (long)blockIdx.x * blockDim.x + threadIdx.x;
    long stride = (long)gridDim.x * blockDim.x;
    for (; i < total; i += stride) {
        long r = i / cols; int c = (int)(i - r*cols);
        float v = in[r*(long)ld + c];
        __half h = __float2half_rn(v);
        oh[i] = h;
        ol[i] = __float2half_rn(v - __half2float(h));
    }
}

__global__ __launch_bounds__(256)
void transpose_convert(const float* __restrict__ in, int N, int Kdim, int remap,
                       __half* __restrict__ oh, __half* __restrict__ ol)
{
    __shared__ float t[32][33];
    int tx = threadIdx.x & 31, ty = threadIdx.x >> 5;
    int k0 = blockIdx.x * 32, n0 = blockIdx.y * 32;
    #pragma unroll
    for (int i = 0; i < 4; i++) {
        int k = k0 + ty + i*8;
        int kr = remap ? ((k >> 6)*128 + (k & 63)) : k;
        int n = n0 + tx;
        t[ty + i*8][tx] = (n < N) ? in[(size_t)kr*N + n] : 0.f;
    }
    __syncthreads();
    #pragma unroll
    for (int i = 0; i < 4; i++) {
        int n = n0 + ty + i*8;
        int k = k0 + tx;
        float v = t[tx][ty + i*8];
        __half h = __float2half_rn(v);
        size_t o = (size_t)n*Kdim + k;
        oh[o] = h;
        ol[o] = __float2half_rn(v - __half2float(h));
    }
}

// =====================================================================
// fp16-split HMMA GEMM with fused epilogues.
// MODE 0: fp32 C (o-proj).
// MODE 1: merged q-proj + ckv-proj. col tiles 0..15 -> Q (rope+split into
//         Qh/Ql), 16..19 -> latent split into a4, 20 -> k_rope (rope +
//         head-broadcast into Kh/Kl cols 64..127).
// MODE 2: kv-up: split into Kh/Kl cols 0..63 (this is also V).
// =====================================================================
#define STAGE_BYTES 32768
#define HG_STAGES   3
#define HG_SMEM     (STAGE_BYTES*HG_STAGES)

template<int MODE>
__global__ __launch_bounds__(256, 1)
void hgemm(const __half* __restrict__ Ah, const __half* __restrict__ Al,
           const __half* __restrict__ Bh, const __half* __restrict__ Bl,
           float* __restrict__ C, int K, int ldc, int Nvalid)
{
    extern __shared__ char smem[];
    const uint32_t sb = smem_u32(smem);
    const int tid  = threadIdx.x;
    const int wid  = tid >> 5, lane = tid & 31;
    const int row0 = blockIdx.y * 128;
    const int wm   = wid >> 1;
    const int wn   = wid & 1;

    const __half* BhP = Bh;
    const __half* BlP = Bl;
    int col0 = blockIdx.x * 128;
    if (MODE == 1 && blockIdx.x >= 16) {
        BhP = g_wah; BlP = g_wal;
        col0 = (blockIdx.x - 16) * 128;
    }

    int l_line[2], l_s8[2], l_r[2], l_c[2];
    #pragma unroll
    for (int j = 0; j < 2; j++) {
        int idx = tid + j*256;
        l_line[j] = idx >> 3;
        l_s8[j]   = idx & 7;
        int v     = l_s8[j] ^ (l_line[j] & 7);
        l_r[j]    = l_line[j]*2 + (v >> 2);
        l_c[j]    = v & 3;
    }

#define LOAD_STAGE(CH, ST) do { \
    uint32_t _base = sb + (uint32_t)(ST)*STAGE_BYTES; \
    _Pragma("unroll") \
    for (int _a = 0; _a < 4; _a++) { \
        const __half* _src = (_a == 0) ? Ah : (_a == 1) ? Al : (_a == 2) ? BhP : BlP; \
        int _rb = (_a < 2) ? row0 : col0; \
        _Pragma("unroll") \
        for (int _j = 0; _j < 2; _j++) { \
            const void* _g = _src + (size_t)(_rb + l_r[_j])*(size_t)K \
                             + (CH)*32 + l_c[_j]*8; \
            CP_ASYNC16(_base + _a*8192u + (uint32_t)(l_line[_j]*128 + l_s8[_j]*16), _g); \
        } \
    } \
    CP_COMMIT(); \
} while (0)

    float acc[2][8][4];
    #pragma unroll
    for (int mi = 0; mi < 2; mi++)
        #pragma unroll
        for (int nj = 0; nj < 8; nj++)
            #pragma unroll
            for (int e = 0; e < 4; e++) acc[mi][nj][e] = 0.f;

    const int nch = K >> 5;
    LOAD_STAGE(0, 0);
    LOAD_STAGE(1, 1);

    const int lr8 = (lane & 7) + ((lane >> 3) & 1)*8;
    const int chx = (lane >> 4);

    int st = 0;
    for (int ch = 0; ch < nch; ch++) {
        if (ch + 2 < nch) { CP_WAIT(1); } else { CP_WAIT(0); }
        __syncthreads();
        if (ch + 2 < nch) {
            int st2 = st + 2; if (st2 >= HG_STAGES) st2 -= HG_STAGES;
            LOAD_STAGE(ch + 2, st2);
        }

        const uint32_t base = sb + (uint32_t)st*STAGE_BYTES;
        #pragma unroll
        for (int kk = 0; kk < 2; kk++) {
            const int cc = kk*2 + chx;
            uint32_t a_h[2][4], a_l[2][4], b_h[4][4], b_l[4][4];

            #pragma unroll
            for (int mi = 0; mi < 2; mi++) {
                int r = wm*32 + mi*16 + lr8;
                uint32_t off = (uint32_t)((r >> 1)*128 +
                    (((cc | ((r & 1) << 2)) ^ ((r >> 1) & 7)) << 4));
                LDSM4(a_h[mi], base + off);
                LDSM4(a_l[mi], base + 8192u + off);
            }
            #pragma unroll
            for (int nb = 0; nb < 4; nb++) {
                int r = wn*64 + nb*16 + lr8;
                uint32_t off = (uint32_t)((r >> 1)*128 +
                    (((cc | ((r & 1) << 2)) ^ ((r >> 1) & 7)) << 4));
                LDSM4(b_h[nb], base + 16384u + off);
                LDSM4(b_l[nb], base + 24576u + off);
            }

            #pragma unroll
            for (int mi = 0; mi < 2; mi++)
                #pragma unroll
                for (int nb = 0; nb < 4; nb++)
                    #pragma unroll
                    for (int nn = 0; nn < 2; nn++) {
                        float* d = acc[mi][nb*2 + nn];
                        MMA16816(d, a_h[mi], b_h[nb][nn], b_h[nb][nn+2]);
                        MMA16816(d, a_h[mi], b_l[nb][nn], b_l[nb][nn+2]);
                        MMA16816(d, a_l[mi], b_h[nb][nn], b_h[nb][nn+2]);
                    }
        }
        st++; if (st >= HG_STAGES) st = 0;
    }

    // ---- fused epilogues ----
    #pragma unroll
    for (int mi = 0; mi < 2; mi++) {
        int m  = row0 + wm*32 + mi*16 + (lane >> 2);
        int tA = m & (TT-1), bbA = m >> 11;
        int tB = tA + 8;                       // same batch (tile 128-aligned)
        #pragma unroll
        for (int nb = 0; nb < 4; nb++)
            #pragma unroll
            for (int nn = 0; nn < 2; nn++) {
                float* d = acc[mi][nb*2 + nn];
                int c = col0 + wn*64 + nb*16 + nn*8 + (lane & 3)*2;

                if (MODE == 0) {
                    if (c < Nvalid) {
                        *(float2*)&C[(size_t)m*ldc + c]       = make_float2(d[0], d[1]);
                        *(float2*)&C[(size_t)(m + 8)*ldc + c] = make_float2(d[2], d[3]);
                    }
                } else if (MODE == 2) {
                    int h = c >> 6, dd = c & 63;
                    size_t b0 = ((size_t)(bbA*HH + h)*TT + tA)*128 + dd;
                    size_t b1 = ((size_t)(bbA*HH + h)*TT + tB)*128 + dd;
                    sstore2(g_Kh, g_Kl, b0, d[0], d[1]);
                    sstore2(g_Kh, g_Kl, b1, d[2], d[3]);
                } else { // MODE 1
                    if (blockIdx.x < 16) {
                        int h = c >> 7, dd = c & 127;
                        float v0 = d[0], v1 = d[1], v2 = d[2], v3 = d[3];
                        if (dd >= 64) {
                            int i = (dd - 64) >> 1;
                            rope2(v0, v1, tA, i);
                            rope2(v2, v3, tB, i);
                        }
                        size_t b0 = ((size_t)(bbA*HH + h)*TT + tA)*128 + dd;
                        size_t b1 = ((size_t)(bbA*HH + h)*TT + tB)*128 + dd;
                        sstore2(g_Qh, g_Ql, b0, v0, v1);
                        sstore2(g_Qh, g_Ql, b1, v2, v3);
                    } else if (blockIdx.x < 20) {
                        sstore2(g_a4h, g_a4l, (size_t)m*512 + c,       d[0], d[1]);
                        sstore2(g_a4h, g_a4l, (size_t)(m + 8)*512 + c, d[2], d[3]);
                    } else {
                        if (c < 576) {
                            int i = (c - 512) >> 1;
                            float v0 = d[0], v1 = d[1], v2 = d[2], v3 = d[3];
                            rope2(v0, v1, tA, i);
                            rope2(v2, v3, tB, i);
                            int dd = 64 + (c - 512);
                            #pragma unroll
                            for (int h2 = 0; h2 < HH; h2++) {
                                size_t b0 = ((size_t)(bbA*HH + h2)*TT + tA)*128 + dd;
                                size_t b1 = ((size_t)(bbA*HH + h2)*TT + tB)*128 + dd;
                                sstore2(g_Kh, g_Kl, b0, v0, v1);
                                sstore2(g_Kh, g_Kl, b1, v2, v3);
                            }
                        }
                    }
                }
            }
    }
}

// =====================================================================
// HMMA causal flash attention. V read from K tile (cols 0..63).
// smem: Qh[0,32K) Ql[32K,64K) + 2 stages of {Kh 16K, Kl 16K}.
// =====================================================================
#define ATM_SCALE 0.08838834764831845f
#define ATM_STAGE 32768
#define ATM_SMEM  (65536 + 2*ATM_STAGE)   /* 131072 */

__global__ __launch_bounds__(256, 1)
void attn_mma(const __half* __restrict__ Qh, const __half* __restrict__ Ql,
              const __half* __restrict__ Kh, const __half* __restrict__ Kl,
              __half* __restrict__ Oh, __half* __restrict__ Ol)
{
    extern __shared__ char smem[];
    const uint32_t sb = smem_u32(smem);
    const int tid  = threadIdx.x;
    const int wm   = tid >> 5, lane = tid & 31;
    const int qt   = (int)gridDim.x - 1 - (int)blockIdx.x;  // heavy CTAs first
    const int h    = blockIdx.y, b = blockIdx.z;
    const int bh   = b*HH + h;
    const int t0   = qt * 128;
    const size_t qrow  = ((size_t)bh*TT + t0)*128;
    const size_t krow0 = (size_t)bh*TT*128;

    // Q (hi/lo) -> swizzled smem (rows 256B, 16 slots of 16B, slot^=(r&7))
    for (int i = tid; i < 2048; i += 256) {
        int r = i >> 4, s = i & 15;
        uint32_t ph = (uint32_t)(r*256 + ((s ^ (r & 7)) << 4));
        *(uint4*)(smem + ph)         = *(const uint4*)(Qh + qrow + (size_t)r*128 + s*8);
        *(uint4*)(smem + 32768 + ph) = *(const uint4*)(Ql + qrow + (size_t)r*128 + s*8);
    }

    const int lr8 = (lane & 7) + ((lane >> 3) & 1)*8;
    const int chx = lane >> 4;

    float o_acc[8][4];
    #pragma unroll
    for (int j = 0; j < 8; j++)
        #pragma unroll
        for (int e = 0; e < 4; e++) o_acc[j][e] = 0.f;
    float m0 = -1e30f, m1 = -1e30f, l0 = 0.f, l1 = 0.f;

    const int nkt = 2*qt + 2;

#define ATM_PRE(KT, ST) do { \
    uint32_t bs = sb + 65536 + (uint32_t)(ST)*ATM_STAGE; \
    const __half* kh_ = Kh + krow0 + (size_t)(KT)*64*128; \
    const __half* kl_ = Kl + krow0 + (size_t)(KT)*64*128; \
    for (int i = tid; i < 1024; i += 256) { \
        int r = i >> 4, s = i & 15; \
        uint32_t ph = (uint32_t)(r*256 + ((s ^ (r & 7)) << 4)); \
        CP_ASYNC16(bs + ph,         kh_ + (size_t)r*128 + s*8); \
        CP_ASYNC16(bs + 16384 + ph, kl_ + (size_t)r*128 + s*8); \
    } \
    CP_COMMIT(); \
} while (0)

    ATM_PRE(0, 0);

    for (int kt = 0; kt < nkt; kt++) {
        const int st = kt & 1;
        CP_WAIT(0);
        __syncthreads();
        if (kt + 1 < nkt) ATM_PRE(kt + 1, st ^ 1);

        const uint32_t ks = sb + 65536 + (uint32_t)st*ATM_STAGE;

        // ---- S = Q K^T  (3-way split) ----
        float sacc[8][4];
        #pragma unroll
        for (int j = 0; j < 8; j++)
            #pragma unroll
            for (int e = 0; e < 4; e++) sacc[j][e] = 0.f;

        #pragma unroll
        for (int cc = 0; cc < 8; cc++) {
            uint32_t aqh[4], aql[4];
            {
                int r = wm*16 + lr8;
                int s = cc*2 + chx;
                uint32_t off = (uint32_t)(r*256 + ((s ^ (r & 7)) << 4));
                LDSM4(aqh, sb + off);
                LDSM4(aql, sb + 32768u + off);
            }
            #pragma unroll
            for (int nb = 0; nb < 4; nb++) {
                uint32_t bkh[4], bkl[4];
                int rn = nb*16 + lr8;
                int s = cc*2 + chx;
                uint32_t off = (uint32_t)(rn*256 + ((s ^ (rn & 7)) << 4));
                LDSM4(bkh, ks + off);
                LDSM4(bkl, ks + 16384u + off);
                MMA16816(sacc[nb*2],     aqh, bkh[0], bkh[2]);
                MMA16816(sacc[nb*2],     aqh, bkl[0], bkl[2]);
                MMA16816(sacc[nb*2],     aql, bkh[0], bkh[2]);
                MMA16816(sacc[nb*2 + 1], aqh, bkh[1], bkh[3]);
                MMA16816(sacc[nb*2 + 1], aqh, bkl[1], bkl[3]);
                MMA16816(sacc[nb*2 + 1], aql, bkh[1], bkh[3]);
            }
        }

        // ---- causal mask ----
        if (kt >= 2*qt) {
            int s0 = kt*64;
            int rb = t0 + wm*16 + (lane >> 2);
            #pragma unroll
            for (int j = 0; j < 8; j++) {
                int c0 = s0 + j*8 + (lane & 3)*2;
                if (c0     > rb)     sacc[j][0] = -3.0e38f;
                if (c0 + 1 > rb)     sacc[j][1] = -3.0e38f;
                if (c0     > rb + 8) sacc[j][2] = -3.0e38f;
                if (c0 + 1 > rb + 8) sacc[j][3] = -3.0e38f;
            }
        }

        // ---- online softmax ----
        float rm0 = -3.0e38f, rm1 = -3.0e38f;
        #pragma unroll
        for (int j = 0; j < 8; j++) {
            rm0 = fmaxf(rm0, fmaxf(sacc[j][0], sacc[j][1]));
            rm1 = fmaxf(rm1, fmaxf(sacc[j][2], sacc[j][3]));
        }
        rm0 = fmaxf(rm0, __shfl_xor_sync(0xffffffffu, rm0, 1));
        rm0 = fmaxf(rm0, __shfl_xor_sync(0xffffffffu, rm0, 2));
        rm1 = fmaxf(rm1, __shfl_xor_sync(0xffffffffu, rm1, 1));
        rm1 = fmaxf(rm1, __shfl_xor_sync(0xffffffffu, rm1, 2));
        float mn0 = fmaxf(m0, rm0), mn1 = fmaxf(m1, rm1);
        float f0  = __expf(ATM_SCALE*(m0 - mn0));
        float f1  = __expf(ATM_SCALE*(m1 - mn1));
        m0 = mn0; m1 = mn1;
        float rs0 = 0.f, rs1 = 0.f;
        #pragma unroll
        for (int j = 0; j < 8; j++) {
            sacc[j][0] = __expf(ATM_SCALE*(sacc[j][0] - mn0)); rs0 += sacc[j][0];
            sacc[j][1] = __expf(ATM_SCALE*(sacc[j][1] - mn0)); rs0 += sacc[j][1];
            sacc[j][2] = __expf(ATM_SCALE*(sacc[j][2] - mn1)); rs1 += sacc[j][2];
            sacc[j][3] = __expf(ATM_SCALE*(sacc[j][3] - mn1)); rs1 += sacc[j][3];
        }
        rs0 += __shfl_xor_sync(0xffffffffu, rs0, 1);
        rs0 += __shfl_xor_sync(0xffffffffu, rs0, 2);
        rs1 += __shfl_xor_sync(0xffffffffu, rs1, 1);
        rs1 += __shfl_xor_sync(0xffffffffu, rs1, 2);
        l0 = l0*f0 + rs0; l1 = l1*f1 + rs1;
        #pragma unroll
        for (int j = 0; j < 8; j++) {
            o_acc[j][0] *= f0; o_acc[j][1] *= f0;
            o_acc[j][2] *= f1; o_acc[j][3] *= f1;
        }

        // ---- P fragments (C-layout -> A-layout) ----
        uint32_t pf[4][4];
        #pragma unroll
        for (int kk = 0; kk < 4; kk++) {
            pf[kk][0] = h2u(__floats2half2_rn(sacc[2*kk][0],     sacc[2*kk][1]));
            pf[kk][1] = h2u(__floats2half2_rn(sacc[2*kk][2],     sacc[2*kk][3]));
            pf[kk][2] = h2u(__floats2half2_rn(sacc[2*kk + 1][0], sacc[2*kk + 1][1]));
            pf[kk][3] = h2u(__floats2half2_rn(sacc[2*kk + 1][2], sacc[2*kk + 1][3]));
        }

        // ---- O += P V  (V = K cols 0..63, read from K tile) ----
        #pragma unroll
        for (int kk = 0; kk < 4; kk++) {
            #pragma unroll
            for (int nb = 0; nb < 4; nb++) {
                uint32_t bvh[4], bvl[4];
                int rv = kk*16 + lr8;
                int s = nb*2 + chx;      // 0..7: stays in first 128B of K row
                uint32_t off = (uint32_t)(rv*256 + ((s ^ (rv & 7)) << 4));
                LDSM4T(bvh, ks + off);
                LDSM4T(bvl, ks + 16384u + off);
                MMA16816(o_acc[nb*2],     pf[kk], bvh[0], bvh[1]);
                MMA16816(o_acc[nb*2],     pf[kk], bvl[0], bvl[1]);
                MMA16816(o_acc[nb*2 + 1], pf[kk], bvh[2], bvh[3]);
                MMA16816(o_acc[nb*2 + 1], pf[kk], bvl[2], bvl[3]);
            }
        }
    }

    // ---- epilogue: normalize + hi/lo split into o-proj operand ----
    float il0 = 1.0f/l0, il1 = 1.0f/l1;
    int r0g = b*TT + t0 + wm*16 + (lane >> 2);
    size_t ob0 = (size_t)r0g*KVW + h*64;
    size_t ob1 = ob0 + (size_t)8*KVW;
    #pragma unroll
    for (int j = 0; j < 8; j++) {
        int d = j*8 + (lane & 3)*2;
        sstore2(Oh, Ol, ob0 + d, o_acc[j][0]*il0, o_acc[j][1]*il0);
        sstore2(Oh, Ol, ob1 + d, o_acc[j][2]*il1, o_acc[j][3]*il1);
    }
}

// =====================================================================
// launch
// =====================================================================
extern "C" void kernel_launch(void* const* d_in, const int* in_sizes, int n_in,
                              void* d_out, int out_size)
{
    const float* x    = (const float*)d_in[0];
    const float* Wq   = (const float*)d_in[1];
    const float* Wkva = (const float*)d_in[2];
    const float* Wkvb = (const float*)d_in[3];
    const float* Wo   = (const float*)d_in[4];
    float* out        = (float*)d_out;

    __half *xh,*xl,*wqh,*wql,*wah,*wal,*wbh,*wbl,*woh,*wol,*a4h,*a4l,*a6h,*a6l;
    __half *Qh,*Ql,*Kh,*Kl;
    cudaGetSymbolAddress((void**)&xh,  g_xh);  cudaGetSymbolAddress((void**)&xl,  g_xl);
    cudaGetSymbolAddress((void**)&wqh, g_wqh); cudaGetSymbolAddress((void**)&wql, g_wql);
    cudaGetSymbolAddress((void**)&wah, g_wah); cudaGetSymbolAddress((void**)&wal, g_wal);
    cudaGetSymbolAddress((void**)&wbh, g_wbh); cudaGetSymbolAddress((void**)&wbl, g_wbl);
    cudaGetSymbolAddress((void**)&woh, g_woh); cudaGetSymbolAddress((void**)&wol, g_wol);
    cudaGetSymbolAddress((void**)&a4h, g_a4h); cudaGetSymbolAddress((void**)&a4l, g_a4l);
    cudaGetSymbolAddress((void**)&a6h, g_a6h); cudaGetSymbolAddress((void**)&a6l, g_a6l);
    cudaGetSymbolAddress((void**)&Qh,  g_Qh);  cudaGetSymbolAddress((void**)&Ql,  g_Ql);
    cudaGetSymbolAddress((void**)&Kh,  g_Kh);  cudaGetSymbolAddress((void**)&Kl,  g_Kl);

    cudaFuncSetAttribute(hgemm<0>, cudaFuncAttributeMaxDynamicSharedMemorySize, HG_SMEM);
    cudaFuncSetAttribute(hgemm<1>, cudaFuncAttributeMaxDynamicSharedMemorySize, HG_SMEM);
    cudaFuncSetAttribute(hgemm<2>, cudaFuncAttributeMaxDynamicSharedMemorySize, HG_SMEM);
    cudaFuncSetAttribute(attn_mma, cudaFuncAttributeMaxDynamicSharedMemorySize, ATM_SMEM);

    dim3 blk(256);

    // weight prep: transpose to [N][K] K-major + hi/lo fp16 split
    transpose_convert<<<dim3(2048/32, 2048/32), blk>>>(Wq,   2048, 2048, 0, wqh, wql);
    transpose_convert<<<dim3(2048/32, NAPAD/32), blk>>>(Wkva, CKVW, 2048, 0, wah, wal);
    transpose_convert<<<dim3(512/32,  1024/32), blk>>>(Wkvb, 1024, 512,  0, wbh, wbl);
    transpose_convert<<<dim3(1024/32, 2048/32), blk>>>(Wo,   2048, 1024, 1, woh, wol);

    // x -> hi/lo
    convert_rows<<<4096, blk>>>(x, CCH, (long)MTOT*CCH, CCH, xh, xl);

    // 1+2) merged q-proj + ckv-proj (fused rope + splits into Qh/Ql, a4, Kh/Kl rope)
    hgemm<1><<<dim3(21, MTOT/128), blk, HG_SMEM>>>(xh, xl, wqh, wql, nullptr,
        2048, 0, 0);

    // 3) kv-up: latent @ Wkvb -> Kh/Kl cols 0..63 (== V)
    hgemm<2><<<dim3(8, MTOT/128), blk, HG_SMEM>>>(a4h, a4l, wbh, wbl, nullptr,
        512, 0, 0);

    // 4) attention -> a6h/a6l (o-proj operand)
    attn_mma<<<dim3(TT/128, HH, BB), blk, ATM_SMEM>>>(Qh, Ql, Kh, Kl, a6h, a6l);

    // 5) out = y_nope @ Wo[nope rows]
    hgemm<0><<<dim3(16, MTOT/128), blk, HG_SMEM>>>(a6h, a6l, woh, wol, out,
        1024, 2048, 2048);
}

// round 11
// speedup vs baseline: 1.5944x; 1.5944x over previous
#include <cuda_runtime.h>
#include <cuda_fp16.h>
#include <stdint.h>
#include <math.h>
#include <float.h>

// ---------------- problem constants ----------------
#define BB    2
#define TT    2048
#define CCH   2048
#define HH    16
#define HDD   128
#define LORA_ 512
#define RDIM  64
#define NDIM  64
#define MTOT  (BB*TT)        /* 4096 */
#define CKVW  (LORA_+RDIM)   /* 576  */
#define KVW   (HH*NDIM)      /* 1024 */
#define NAPAD 640

// ---------------- fp32 scratch ----------------
__device__ float g_qf  [(size_t)MTOT * 2048];   // q projection (pre-rope)
__device__ float g_ckvf[(size_t)MTOT * CKVW];   // [latent 512 | k_rope 64]

// ---------------- fp16 split (hi/lo) buffers ----------------
__device__ __align__(128) __half g_xh [(size_t)MTOT*CCH],  g_xl [(size_t)MTOT*CCH];
__device__ __align__(128) __half g_wqh[(size_t)2048*2048], g_wql[(size_t)2048*2048];
__device__ __align__(128) __half g_wah[(size_t)NAPAD*2048],g_wal[(size_t)NAPAD*2048];
__device__ __align__(128) __half g_wbh[(size_t)1024*512],  g_wbl[(size_t)1024*512];
__device__ __align__(128) __half g_woh[(size_t)2048*1024], g_wol[(size_t)2048*1024];
__device__ __align__(128) __half g_a4h[(size_t)MTOT*512],  g_a4l[(size_t)MTOT*512];
__device__ __align__(128) __half g_a6h[(size_t)MTOT*1024], g_a6l[(size_t)MTOT*1024];
// attention operands [bh][t][d]; V == K[:, 0:64]
__device__ __align__(128) __half g_Qh[(size_t)BB*HH*TT*128], g_Ql[(size_t)BB*HH*TT*128];
__device__ __align__(128) __half g_Kh[(size_t)BB*HH*TT*128], g_Kl[(size_t)BB*HH*TT*128];

// =====================================================================
// PTX helpers (baseline sm_80+ — compile at compute_103)
// =====================================================================
__device__ __forceinline__ uint32_t smem_u32(const void* p) {
    uint32_t a;
    asm("{ .reg .u64 t; cvta.to.shared.u64 t, %1; cvt.u32.u64 %0, t; }" : "=r"(a) : "l"(p));
    return a;
}
#define CP_ASYNC16(dst, src) \
    asm volatile("cp.async.cg.shared.global [%0], [%1], 16;" :: "r"(dst), "l"(src))
#define CP_COMMIT() asm volatile("cp.async.commit_group;" ::: "memory")
#define CP_WAIT(n)  asm volatile("cp.async.wait_group %0;" :: "n"(n) : "memory")

#define LDSM4(R, addr) \
    asm volatile("ldmatrix.sync.aligned.m8n8.x4.shared.b16 {%0,%1,%2,%3}, [%4];" \
        : "=r"((R)[0]), "=r"((R)[1]), "=r"((R)[2]), "=r"((R)[3]) : "r"(addr))
#define LDSM4T(R, addr) \
    asm volatile("ldmatrix.sync.aligned.m8n8.x4.trans.shared.b16 {%0,%1,%2,%3}, [%4];" \
        : "=r"((R)[0]), "=r"((R)[1]), "=r"((R)[2]), "=r"((R)[3]) : "r"(addr))

#define MMA16816(D, A, B0, B1) \
    asm volatile("mma.sync.aligned.m16n8k16.row.col.f32.f16.f16.f32 " \
        "{%0,%1,%2,%3}, {%4,%5,%6,%7}, {%8,%9}, {%0,%1,%2,%3};" \
        : "+f"((D)[0]), "+f"((D)[1]), "+f"((D)[2]), "+f"((D)[3]) \
        : "r"((A)[0]), "r"((A)[1]), "r"((A)[2]), "r"((A)[3]), "r"(B0), "r"(B1))

__device__ __forceinline__ uint32_t h2u(__half2 v) { return *(uint32_t*)&v; }

// hi/lo split store of a (v0,v1) pair
__device__ __forceinline__ void sstore2(__half* __restrict__ oh, __half* __restrict__ ol,
                                        size_t idx, float v0, float v1)
{
    __half h0 = __float2half_rn(v0), h1 = __float2half_rn(v1);
    *(__half2*)(oh + idx) = __halves2half2(h0, h1);
    *(__half2*)(ol + idx) = __halves2half2(__float2half_rn(v0 - __half2float(h0)),
                                           __float2half_rn(v1 - __half2float(h1)));
}

// RoPE: freq_i = theta^(-i/32) = 2^(-i*log2(1e5)/32)
#define ROPE_L2F 0.5190512648261504f
__device__ __forceinline__ void rope2(float& v0, float& v1, int t, int i)
{
    float freq = exp2f(-ROPE_L2F * (float)i);
    float sn, cs; sincosf((float)t * freq, &sn, &cs);
    float a = v0*cs - v1*sn;
    float b = v0*sn + v1*cs;
    v0 = a; v1 = b;
}

// =====================================================================
// conversions (prep)
// =====================================================================
__global__ __launch_bounds__(256)
void convert_rows(const float* __restrict__ in, int ld, long total, int cols,
                  __half* __restrict__ oh, __half* __restrict__ ol)
{
    long i = (long)blockIdx.x * blockDim.x + threadIdx.x;
    long stride = (long)gridDim.x * blockDim.x;
    for (; i < total; i += stride) {
        long r = i / cols; int c = (int)(i - r*cols);
        float v = in[r*(long)ld + c];
        __half h = __float2half_rn(v);
        oh[i] = h;
        ol[i] = __float2half_rn(v - __half2float(h));
    }
}

__global__ __launch_bounds__(256)
void transpose_convert(const float* __restrict__ in, int N, int Kdim, int remap,
                       __half* __restrict__ oh, __half* __restrict__ ol)
{
    __shared__ float t[32][33];
    int tx = threadIdx.x & 31, ty = threadIdx.x >> 5;
    int k0 = blockIdx.x * 32, n0 = blockIdx.y * 32;
    #pragma unroll
    for (int i = 0; i < 4; i++) {
        int k = k0 + ty + i*8;
        int kr = remap ? ((k >> 6)*128 + (k & 63)) : k;
        int n = n0 + tx;
        t[ty + i*8][tx] = (n < N) ? in[(size_t)kr*N + n] : 0.f;
    }
    __syncthreads();
    #pragma unroll
    for (int i = 0; i < 4; i++) {
        int n = n0 + ty + i*8;
        int k = k0 + tx;
        float v = t[tx][ty + i*8];
        __half h = __float2half_rn(v);
        size_t o = (size_t)n*Kdim + k;
        oh[o] = h;
        ol[o] = __float2half_rn(v - __half2float(h));
    }
}

// Q: [bh][t][128] <- g_qf[(b*T+t)][h*128+d], rope applied to d>=64
__global__ __launch_bounds__(256)
void conv_q(const float* __restrict__ q, __half* __restrict__ oh, __half* __restrict__ ol)
{
    long i4 = (long)blockIdx.x*blockDim.x + threadIdx.x;
    if (i4 >= (long)BB*HH*TT*32) return;
    long i = i4*4;
    int d = (int)(i & 127); long r = i >> 7;
    int t = (int)(r & (TT-1)); int bh = (int)(r >> 11);
    int hh = bh & 15, bb = bh >> 4;
    float4 v = *(const float4*)&q[((size_t)(bb*TT + t))*2048 + hh*128 + d];
    if (d >= 64) {
        int i0 = (d - 64) >> 1;
        rope2(v.x, v.y, t, i0);
        rope2(v.z, v.w, t, i0 + 1);
    }
    __half h0 = __float2half_rn(v.x), h1 = __float2half_rn(v.y);
    __half h2 = __float2half_rn(v.z), h3 = __float2half_rn(v.w);
    *(__half2*)(oh + i)     = __halves2half2(h0, h1);
    *(__half2*)(oh + i + 2) = __halves2half2(h2, h3);
    *(__half2*)(ol + i)     = __halves2half2(__float2half_rn(v.x - __half2float(h0)),
                                             __float2half_rn(v.y - __half2float(h1)));
    *(__half2*)(ol + i + 2) = __halves2half2(__float2half_rn(v.z - __half2float(h2)),
                                             __float2half_rn(v.w - __half2float(h3)));
}

// k_rope: rope'd ckv cols 512..575 broadcast into Kh/Kl cols 64..127, all heads
__global__ __launch_bounds__(256)
void conv_krope(const float* __restrict__ ckv,
                __half* __restrict__ Kh, __half* __restrict__ Kl)
{
    int idx = blockIdx.x*blockDim.x + threadIdx.x;     // over BB*TT*32
    if (idx >= BB*TT*32) return;
    int i = idx & 31;
    int m = idx >> 5;
    int t = m & (TT-1), b = m >> 11;
    float2 v = *(const float2*)&ckv[(size_t)m*CKVW + LORA_ + 2*i];
    rope2(v.x, v.y, t, i);
    __half h0 = __float2half_rn(v.x), h1 = __float2half_rn(v.y);
    __half2 hi = __halves2half2(h0, h1);
    __half2 lo = __halves2half2(__float2half_rn(v.x - __half2float(h0)),
                                __float2half_rn(v.y - __half2float(h1)));
    size_t base = ((size_t)(b*HH)*TT + t)*128 + 64 + 2*i;
    #pragma unroll
    for (int h = 0; h < HH; h++) {
        *(__half2*)(Kh + base) = hi;
        *(__half2*)(Kl + base) = lo;
        base += (size_t)TT*128;
    }
}

// =====================================================================
// fp16-split HMMA GEMM. Epilogues are arithmetic-free:
// MODE 0: fp32 C (o-proj).
// MODE 1: merged q-proj + ckv-proj -> fp32 g_qf / g_ckvf.
// MODE 2: kv-up -> hi/lo split into Kh/Kl cols 0..63 (== V).
// =====================================================================
#define STAGE_BYTES 32768
#define HG_STAGES   3
#define HG_SMEM     (STAGE_BYTES*HG_STAGES)

template<int MODE>
__global__ __launch_bounds__(256, 1)
void hgemm(const __half* __restrict__ Ah, const __half* __restrict__ Al,
           const __half* __restrict__ Bh, const __half* __restrict__ Bl,
           float* __restrict__ C, int K, int ldc, int Nvalid)
{
    extern __shared__ char smem[];
    const uint32_t sb = smem_u32(smem);
    const int tid  = threadIdx.x;
    const int wid  = tid >> 5, lane = tid & 31;
    const int row0 = blockIdx.y * 128;
    const int wm   = wid >> 1;
    const int wn   = wid & 1;

    const __half* BhP = Bh;
    const __half* BlP = Bl;
    int col0 = blockIdx.x * 128;
    if (MODE == 1 && blockIdx.x >= 16) {
        BhP = g_wah; BlP = g_wal;
        col0 = (blockIdx.x - 16) * 128;
    }

    int l_line[2], l_s8[2], l_r[2], l_c[2];
    #pragma unroll
    for (int j = 0; j < 2; j++) {
        int idx = tid + j*256;
        l_line[j] = idx >> 3;
        l_s8[j]   = idx & 7;
        int v     = l_s8[j] ^ (l_line[j] & 7);
        l_r[j]    = l_line[j]*2 + (v >> 2);
        l_c[j]    = v & 3;
    }

#define LOAD_STAGE(CH, ST) do { \
    uint32_t _base = sb + (uint32_t)(ST)*STAGE_BYTES; \
    _Pragma("unroll") \
    for (int _a = 0; _a < 4; _a++) { \
        const __half* _src = (_a == 0) ? Ah : (_a == 1) ? Al : (_a == 2) ? BhP : BlP; \
        int _rb = (_a < 2) ? row0 : col0; \
        _Pragma("unroll") \
        for (int _j = 0; _j < 2; _j++) { \
            const void* _g = _src + (size_t)(_rb + l_r[_j])*(size_t)K \
                             + (CH)*32 + l_c[_j]*8; \
            CP_ASYNC16(_base + _a*8192u + (uint32_t)(l_line[_j]*128 + l_s8[_j]*16), _g); \
        } \
    } \
    CP_COMMIT(); \
} while (0)

    float acc[2][8][4];
    #pragma unroll
    for (int mi = 0; mi < 2; mi++)
        #pragma unroll
        for (int nj = 0; nj < 8; nj++)
            #pragma unroll
            for (int e = 0; e < 4; e++) acc[mi][nj][e] = 0.f;

    const int nch = K >> 5;
    LOAD_STAGE(0, 0);
    LOAD_STAGE(1, 1);

    const int lr8 = (lane & 7) + ((lane >> 3) & 1)*8;
    const int chx = (lane >> 4);

    int st = 0;
    for (int ch = 0; ch < nch; ch++) {
        if (ch + 2 < nch) { CP_WAIT(1); } else { CP_WAIT(0); }
        __syncthreads();
        if (ch + 2 < nch) {
            int st2 = st + 2; if (st2 >= HG_STAGES) st2 -= HG_STAGES;
            LOAD_STAGE(ch + 2, st2);
        }

        const uint32_t base = sb + (uint32_t)st*STAGE_BYTES;
        #pragma unroll
        for (int kk = 0; kk < 2; kk++) {
            const int cc = kk*2 + chx;
            uint32_t a_h[2][4], a_l[2][4], b_h[4][4], b_l[4][4];

            #pragma unroll
            for (int mi = 0; mi < 2; mi++) {
                int r = wm*32 + mi*16 + lr8;
                uint32_t off = (uint32_t)((r >> 1)*128 +
                    (((cc | ((r & 1) << 2)) ^ ((r >> 1) & 7)) << 4));
                LDSM4(a_h[mi], base + off);
                LDSM4(a_l[mi], base + 8192u + off);
            }
            #pragma unroll
            for (int nb = 0; nb < 4; nb++) {
                int r = wn*64 + nb*16 + lr8;
                uint32_t off = (uint32_t)((r >> 1)*128 +
                    (((cc | ((r & 1) << 2)) ^ ((r >> 1) & 7)) << 4));
                LDSM4(b_h[nb], base + 16384u + off);
                LDSM4(b_l[nb], base + 24576u + off);
            }

            #pragma unroll
            for (int mi = 0; mi < 2; mi++)
                #pragma unroll
                for (int nb = 0; nb < 4; nb++)
                    #pragma unroll
                    for (int nn = 0; nn < 2; nn++) {
                        float* d = acc[mi][nb*2 + nn];
                        MMA16816(d, a_h[mi], b_h[nb][nn], b_h[nb][nn+2]);
                        MMA16816(d, a_h[mi], b_l[nb][nn], b_l[nb][nn+2]);
                        MMA16816(d, a_l[mi], b_h[nb][nn], b_h[nb][nn+2]);
                    }
        }
        st++; if (st >= HG_STAGES) st = 0;
    }

    // ---- epilogues (no transcendentals, no heavy branching) ----
    #pragma unroll
    for (int mi = 0; mi < 2; mi++) {
        int m = row0 + wm*32 + mi*16 + (lane >> 2);
        #pragma unroll
        for (int nb = 0; nb < 4; nb++)
            #pragma unroll
            for (int nn = 0; nn < 2; nn++) {
                float* d = acc[mi][nb*2 + nn];
                int c = col0 + wn*64 + nb*16 + nn*8 + (lane & 3)*2;

                if (MODE == 0) {
                    if (c < Nvalid) {
                        *(float2*)&C[(size_t)m*ldc + c]       = make_float2(d[0], d[1]);
                        *(float2*)&C[(size_t)(m + 8)*ldc + c] = make_float2(d[2], d[3]);
                    }
                } else if (MODE == 1) {
                    if (blockIdx.x < 16) {
                        *(float2*)&g_qf[(size_t)m*2048 + c]       = make_float2(d[0], d[1]);
                        *(float2*)&g_qf[(size_t)(m + 8)*2048 + c] = make_float2(d[2], d[3]);
                    } else if (c < CKVW) {
                        *(float2*)&g_ckvf[(size_t)m*CKVW + c]       = make_float2(d[0], d[1]);
                        *(float2*)&g_ckvf[(size_t)(m + 8)*CKVW + c] = make_float2(d[2], d[3]);
                    }
                } else { // MODE 2: kv-up -> Kh/Kl nope cols
                    int tA = m & (TT-1), bbA = m >> 11;
                    int h = c >> 6, dd = c & 63;
                    size_t b0 = ((size_t)(bbA*HH + h)*TT + tA)*128 + dd;
                    sstore2(g_Kh, g_Kl, b0, d[0], d[1]);
                    sstore2(g_Kh, g_Kl, b0 + (size_t)8*128, d[2], d[3]);
                }
            }
    }
}

// =====================================================================
// HMMA causal flash attention. V read from K tile (cols 0..63).
// smem: Qh[0,32K) Ql[32K,64K) + 2 stages of {Kh 16K, Kl 16K}.
// =====================================================================
#define ATM_SCALE 0.08838834764831845f
#define ATM_STAGE 32768
#define ATM_SMEM  (65536 + 2*ATM_STAGE)   /* 131072 */

__global__ __launch_bounds__(256, 1)
void attn_mma(const __half* __restrict__ Qh, const __half* __restrict__ Ql,
              const __half* __restrict__ Kh, const __half* __restrict__ Kl,
              __half* __restrict__ Oh, __half* __restrict__ Ol)
{
    extern __shared__ char smem[];
    const uint32_t sb = smem_u32(smem);
    const int tid  = threadIdx.x;
    const int wm   = tid >> 5, lane = tid & 31;
    const int qt   = (int)gridDim.x - 1 - (int)blockIdx.x;
    const int h    = blockIdx.y, b = blockIdx.z;
    const int bh   = b*HH + h;
    const int t0   = qt * 128;
    const size_t qrow  = ((size_t)bh*TT + t0)*128;
    const size_t krow0 = (size_t)bh*TT*128;

    for (int i = tid; i < 2048; i += 256) {
        int r = i >> 4, s = i & 15;
        uint32_t ph = (uint32_t)(r*256 + ((s ^ (r & 7)) << 4));
        *(uint4*)(smem + ph)         = *(const uint4*)(Qh + qrow + (size_t)r*128 + s*8);
        *(uint4*)(smem + 32768 + ph) = *(const uint4*)(Ql + qrow + (size_t)r*128 + s*8);
    }

    const int lr8 = (lane & 7) + ((lane >> 3) & 1)*8;
    const int chx = lane >> 4;

    float o_acc[8][4];
    #pragma unroll
    for (int j = 0; j < 8; j++)
        #pragma unroll
        for (int e = 0; e < 4; e++) o_acc[j][e] = 0.f;
    float m0 = -1e30f, m1 = -1e30f, l0 = 0.f, l1 = 0.f;

    const int nkt = 2*qt + 2;

#define ATM_PRE(KT, ST) do { \
    uint32_t bs = sb + 65536 + (uint32_t)(ST)*ATM_STAGE; \
    const __half* kh_ = Kh + krow0 + (size_t)(KT)*64*128; \
    const __half* kl_ = Kl + krow0 + (size_t)(KT)*64*128; \
    for (int i = tid; i < 1024; i += 256) { \
        int r = i >> 4, s = i & 15; \
        uint32_t ph = (uint32_t)(r*256 + ((s ^ (r & 7)) << 4)); \
        CP_ASYNC16(bs + ph,         kh_ + (size_t)r*128 + s*8); \
        CP_ASYNC16(bs + 16384 + ph, kl_ + (size_t)r*128 + s*8); \
    } \
    CP_COMMIT(); \
} while (0)

    ATM_PRE(0, 0);

    for (int kt = 0; kt < nkt; kt++) {
        const int st = kt & 1;
        CP_WAIT(0);
        __syncthreads();
        if (kt + 1 < nkt) ATM_PRE(kt + 1, st ^ 1);

        const uint32_t ks = sb + 65536 + (uint32_t)st*ATM_STAGE;

        float sacc[8][4];
        #pragma unroll
        for (int j = 0; j < 8; j++)
            #pragma unroll
            for (int e = 0; e < 4; e++) sacc[j][e] = 0.f;

        #pragma unroll
        for (int cc = 0; cc < 8; cc++) {
            uint32_t aqh[4], aql[4];
            {
                int r = wm*16 + lr8;
                int s = cc*2 + chx;
                uint32_t off = (uint32_t)(r*256 + ((s ^ (r & 7)) << 4));
                LDSM4(aqh, sb + off);
                LDSM4(aql, sb + 32768u + off);
            }
            #pragma unroll
            for (int nb = 0; nb < 4; nb++) {
                uint32_t bkh[4], bkl[4];
                int rn = nb*16 + lr8;
                int s = cc*2 + chx;
                uint32_t off = (uint32_t)(rn*256 + ((s ^ (rn & 7)) << 4));
                LDSM4(bkh, ks + off);
                LDSM4(bkl, ks + 16384u + off);
                MMA16816(sacc[nb*2],     aqh, bkh[0], bkh[2]);
                MMA16816(sacc[nb*2],     aqh, bkl[0], bkl[2]);
                MMA16816(sacc[nb*2],     aql, bkh[0], bkh[2]);
                MMA16816(sacc[nb*2 + 1], aqh, bkh[1], bkh[3]);
                MMA16816(sacc[nb*2 + 1], aqh, bkl[1], bkl[3]);
                MMA16816(sacc[nb*2 + 1], aql, bkh[1], bkh[3]);
            }
        }

        if (kt >= 2*qt) {
            int s0 = kt*64;
            int rb = t0 + wm*16 + (lane >> 2);
            #pragma unroll
            for (int j = 0; j < 8; j++) {
                int c0 = s0 + j*8 + (lane & 3)*2;
                if (c0     > rb)     sacc[j][0] = -3.0e38f;
                if (c0 + 1 > rb)     sacc[j][1] = -3.0e38f;
                if (c0     > rb + 8) sacc[j][2] = -3.0e38f;
                if (c0 + 1 > rb + 8) sacc[j][3] = -3.0e38f;
            }
        }

        float rm0 = -3.0e38f, rm1 = -3.0e38f;
        #pragma unroll
        for (int j = 0; j < 8; j++) {
            rm0 = fmaxf(rm0, fmaxf(sacc[j][0], sacc[j][1]));
            rm1 = fmaxf(rm1, fmaxf(sacc[j][2], sacc[j][3]));
        }
        rm0 = fmaxf(rm0, __shfl_xor_sync(0xffffffffu, rm0, 1));
        rm0 = fmaxf(rm0, __shfl_xor_sync(0xffffffffu, rm0, 2));
        rm1 = fmaxf(rm1, __shfl_xor_sync(0xffffffffu, rm1, 1));
        rm1 = fmaxf(rm1, __shfl_xor_sync(0xffffffffu, rm1, 2));
        float mn0 = fmaxf(m0, rm0), mn1 = fmaxf(m1, rm1);
        float f0  = __expf(ATM_SCALE*(m0 - mn0));
        float f1  = __expf(ATM_SCALE*(m1 - mn1));
        m0 = mn0; m1 = mn1;
        float rs0 = 0.f, rs1 = 0.f;
        #pragma unroll
        for (int j = 0; j < 8; j++) {
            sacc[j][0] = __expf(ATM_SCALE*(sacc[j][0] - mn0)); rs0 += sacc[j][0];
            sacc[j][1] = __expf(ATM_SCALE*(sacc[j][1] - mn0)); rs0 += sacc[j][1];
            sacc[j][2] = __expf(ATM_SCALE*(sacc[j][2] - mn1)); rs1 += sacc[j][2];
            sacc[j][3] = __expf(ATM_SCALE*(sacc[j][3] - mn1)); rs1 += sacc[j][3];
        }
        rs0 += __shfl_xor_sync(0xffffffffu, rs0, 1);
        rs0 += __shfl_xor_sync(0xffffffffu, rs0, 2);
        rs1 += __shfl_xor_sync(0xffffffffu, rs1, 1);
        rs1 += __shfl_xor_sync(0xffffffffu, rs1, 2);
        l0 = l0*f0 + rs0; l1 = l1*f1 + rs1;
        #pragma unroll
        for (int j = 0; j < 8; j++) {
            o_acc[j][0] *= f0; o_acc[j][1] *= f0;
            o_acc[j][2] *= f1; o_acc[j][3] *= f1;
        }

        uint32_t pf[4][4];
        #pragma unroll
        for (int kk = 0; kk < 4; kk++) {
            pf[kk][0] = h2u(__floats2half2_rn(sacc[2*kk][0],     sacc[2*kk][1]));
            pf[kk][1] = h2u(__floats2half2_rn(sacc[2*kk][2],     sacc[2*kk][3]));
            pf[kk][2] = h2u(__floats2half2_rn(sacc[2*kk + 1][0], sacc[2*kk + 1][1]));
            pf[kk][3] = h2u(__floats2half2_rn(sacc[2*kk + 1][2], sacc[2*kk + 1][3]));
        }

        #pragma unroll
        for (int kk = 0; kk < 4; kk++) {
            #pragma unroll
            for (int nb = 0; nb < 4; nb++) {
                uint32_t bvh[4], bvl[4];
                int rv = kk*16 + lr8;
                int s = nb*2 + chx;
                uint32_t off = (uint32_t)(rv*256 + ((s ^ (rv & 7)) << 4));
                LDSM4T(bvh, ks + off);
                LDSM4T(bvl, ks + 16384u + off);
                MMA16816(o_acc[nb*2],     pf[kk], bvh[0], bvh[1]);
                MMA16816(o_acc[nb*2],     pf[kk], bvl[0], bvl[1]);
                MMA16816(o_acc[nb*2 + 1], pf[kk], bvh[2], bvh[3]);
                MMA16816(o_acc[nb*2 + 1], pf[kk], bvl[2], bvl[3]);
            }
        }
    }

    float il0 = 1.0f/l0, il1 = 1.0f/l1;
    int r0g = b*TT + t0 + wm*16 + (lane >> 2);
    size_t ob0 = (size_t)r0g*KVW + h*64;
    size_t ob1 = ob0 + (size_t)8*KVW;
    #pragma unroll
    for (int j = 0; j < 8; j++) {
        int d = j*8 + (lane & 3)*2;
        sstore2(Oh, Ol, ob0 + d, o_acc[j][0]*il0, o_acc[j][1]*il0);
        sstore2(Oh, Ol, ob1 + d, o_acc[j][2]*il1, o_acc[j][3]*il1);
    }
}

// =====================================================================
// launch
// =====================================================================
extern "C" void kernel_launch(void* const* d_in, const int* in_sizes, int n_in,
                              void* d_out, int out_size)
{
    const float* x    = (const float*)d_in[0];
    const float* Wq   = (const float*)d_in[1];
    const float* Wkva = (const float*)d_in[2];
    const float* Wkvb = (const float*)d_in[3];
    const float* Wo   = (const float*)d_in[4];
    float* out        = (float*)d_out;

    float *qf, *ckvf;
    cudaGetSymbolAddress((void**)&qf,   g_qf);
    cudaGetSymbolAddress((void**)&ckvf, g_ckvf);

    __half *xh,*xl,*wqh,*wql,*wah,*wal,*wbh,*wbl,*woh,*wol,*a4h,*a4l,*a6h,*a6l;
    __half *Qh,*Ql,*Kh,*Kl;
    cudaGetSymbolAddress((void**)&xh,  g_xh);  cudaGetSymbolAddress((void**)&xl,  g_xl);
    cudaGetSymbolAddress((void**)&wqh, g_wqh); cudaGetSymbolAddress((void**)&wql, g_wql);
    cudaGetSymbolAddress((void**)&wah, g_wah); cudaGetSymbolAddress((void**)&wal, g_wal);
    cudaGetSymbolAddress((void**)&wbh, g_wbh); cudaGetSymbolAddress((void**)&wbl, g_wbl);
    cudaGetSymbolAddress((void**)&woh, g_woh); cudaGetSymbolAddress((void**)&wol, g_wol);
    cudaGetSymbolAddress((void**)&a4h, g_a4h); cudaGetSymbolAddress((void**)&a4l, g_a4l);
    cudaGetSymbolAddress((void**)&a6h, g_a6h); cudaGetSymbolAddress((void**)&a6l, g_a6l);
    cudaGetSymbolAddress((void**)&Qh,  g_Qh);  cudaGetSymbolAddress((void**)&Ql,  g_Ql);
    cudaGetSymbolAddress((void**)&Kh,  g_Kh);  cudaGetSymbolAddress((void**)&Kl,  g_Kl);

    cudaFuncSetAttribute(hgemm<0>, cudaFuncAttributeMaxDynamicSharedMemorySize, HG_SMEM);
    cudaFuncSetAttribute(hgemm<1>, cudaFuncAttributeMaxDynamicSharedMemorySize, HG_SMEM);
    cudaFuncSetAttribute(hgemm<2>, cudaFuncAttributeMaxDynamicSharedMemorySize, HG_SMEM);
    cudaFuncSetAttribute(attn_mma, cudaFuncAttributeMaxDynamicSharedMemorySize, ATM_SMEM);

    dim3 blk(256);

    // weight prep: transpose to [N][K] K-major + hi/lo fp16 split
    transpose_convert<<<dim3(2048/32, 2048/32), blk>>>(Wq,   2048, 2048, 0, wqh, wql);
    transpose_convert<<<dim3(2048/32, NAPAD/32), blk>>>(Wkva, CKVW, 2048, 0, wah, wal);
    transpose_convert<<<dim3(512/32,  1024/32), blk>>>(Wkvb, 1024, 512,  0, wbh, wbl);
    transpose_convert<<<dim3(1024/32, 2048/32), blk>>>(Wo,   2048, 1024, 1, woh, wol);

    // x -> hi/lo
    convert_rows<<<4096, blk>>>(x, CCH, (long)MTOT*CCH, CCH, xh, xl);

    // 1+2) merged q-proj + ckv-proj -> fp32 g_qf / g_ckvf (plain epilogue)
    hgemm<1><<<dim3(21, MTOT/128), blk, HG_SMEM>>>(xh, xl, wqh, wql, nullptr,
        2048, 0, 0);

    // 3) latent -> hi/lo for kv-up
    convert_rows<<<2048, blk>>>(ckvf, CKVW, (long)MTOT*LORA_, LORA_, a4h, a4l);

    // 4) k_rope: rope + broadcast into Kh/Kl cols 64..127
    conv_krope<<<(BB*TT*32 + 255)/256, blk>>>(ckvf, Kh, Kl);

    // 5) kv-up: latent @ Wkvb -> Kh/Kl cols 0..63 (== V), split-store epilogue
    hgemm<2><<<dim3(8, MTOT/128), blk, HG_SMEM>>>(a4h, a4l, wbh, wbl, nullptr,
        512, 0, 0);

    // 6) q: rope + hi/lo split -> Qh/Ql
    conv_q<<<8192, blk>>>(qf, Qh, Ql);

    // 7) attention -> a6h/a6l (o-proj operand)
    attn_mma<<<dim3(TT/128, HH, BB), blk, ATM_SMEM>>>(Qh, Ql, Kh, Kl, a6h, a6l);

    // 8) out = y_nope @ Wo[nope rows]
    hgemm<0><<<dim3(16, MTOT/128), blk, HG_SMEM>>>(a6h, a6l, woh, wol, out,
        1024, 2048, 2048);
}

// round 13
// speedup vs baseline: 1.6354x; 1.0257x over previous
#include <cuda_runtime.h>
#include <cuda_fp16.h>
#include <stdint.h>
#include <math.h>
#include <float.h>

// ---------------- problem constants ----------------
#define BB    2
#define TT    2048
#define CCH   2048
#define HH    16
#define HDD   128
#define LORA_ 512
#define RDIM  64
#define NDIM  64
#define MTOT  (BB*TT)        /* 4096 */
#define CKVW  (LORA_+RDIM)   /* 576  */
#define KVW   (HH*NDIM)      /* 1024 */
#define NAPAD 640

// ---------------- fp32 scratch ----------------
__device__ float g_qf  [(size_t)MTOT * 2048];   // q projection (pre-rope)
__device__ float g_ckvf[(size_t)MTOT * CKVW];   // only cols 512..575 used (k_rope)

// ---------------- fp16 split (hi/lo) buffers ----------------
__device__ __align__(128) __half g_xh [(size_t)MTOT*CCH],  g_xl [(size_t)MTOT*CCH];
__device__ __align__(128) __half g_wqh[(size_t)2048*2048], g_wql[(size_t)2048*2048];
__device__ __align__(128) __half g_wah[(size_t)NAPAD*2048],g_wal[(size_t)NAPAD*2048];
__device__ __align__(128) __half g_wbh[(size_t)1024*512],  g_wbl[(size_t)1024*512];
__device__ __align__(128) __half g_woh[(size_t)2048*1024], g_wol[(size_t)2048*1024];
__device__ __align__(128) __half g_a4h[(size_t)MTOT*512],  g_a4l[(size_t)MTOT*512];
__device__ __align__(128) __half g_a6h[(size_t)MTOT*1024], g_a6l[(size_t)MTOT*1024];
// attention operands [bh][t][d]; V == K[:, 0:64]
__device__ __align__(128) __half g_Qh[(size_t)BB*HH*TT*128], g_Ql[(size_t)BB*HH*TT*128];
__device__ __align__(128) __half g_Kh[(size_t)BB*HH*TT*128], g_Kl[(size_t)BB*HH*TT*128];

// =====================================================================
// PTX helpers (baseline sm_80+ — compile at compute_103)
// =====================================================================
__device__ __forceinline__ uint32_t smem_u32(const void* p) {
    uint32_t a;
    asm("{ .reg .u64 t; cvta.to.shared.u64 t, %1; cvt.u32.u64 %0, t; }" : "=r"(a) : "l"(p));
    return a;
}
#define CP_ASYNC16(dst, src) \
    asm volatile("cp.async.cg.shared.global [%0], [%1], 16;" :: "r"(dst), "l"(src))
#define CP_COMMIT() asm volatile("cp.async.commit_group;" ::: "memory")
#define CP_WAIT(n)  asm volatile("cp.async.wait_group %0;" :: "n"(n) : "memory")

#define LDSM4(R, addr) \
    asm volatile("ldmatrix.sync.aligned.m8n8.x4.shared.b16 {%0,%1,%2,%3}, [%4];" \
        : "=r"((R)[0]), "=r"((R)[1]), "=r"((R)[2]), "=r"((R)[3]) : "r"(addr))
#define LDSM4T(R, addr) \
    asm volatile("ldmatrix.sync.aligned.m8n8.x4.trans.shared.b16 {%0,%1,%2,%3}, [%4];" \
        : "=r"((R)[0]), "=r"((R)[1]), "=r"((R)[2]), "=r"((R)[3]) : "r"(addr))

#define MMA16816(D, A, B0, B1) \
    asm volatile("mma.sync.aligned.m16n8k16.row.col.f32.f16.f16.f32 " \
        "{%0,%1,%2,%3}, {%4,%5,%6,%7}, {%8,%9}, {%0,%1,%2,%3};" \
        : "+f"((D)[0]), "+f"((D)[1]), "+f"((D)[2]), "+f"((D)[3]) \
        : "r"((A)[0]), "r"((A)[1]), "r"((A)[2]), "r"((A)[3]), "r"(B0), "r"(B1))

__device__ __forceinline__ uint32_t h2u(__half2 v) { return *(uint32_t*)&v; }

// hi/lo split store of a (v0,v1) pair
__device__ __forceinline__ void sstore2(__half* __restrict__ oh, __half* __restrict__ ol,
                                        size_t idx, float v0, float v1)
{
    __half h0 = __float2half_rn(v0), h1 = __float2half_rn(v1);
    *(__half2*)(oh + idx) = __halves2half2(h0, h1);
    *(__half2*)(ol + idx) = __halves2half2(__float2half_rn(v0 - __half2float(h0)),
                                           __float2half_rn(v1 - __half2float(h1)));
}

// RoPE: freq_i = theta^(-i/32) = 2^(-i*log2(1e5)/32)
#define ROPE_L2F 0.5190512648261504f
__device__ __forceinline__ void rope2(float& v0, float& v1, int t, int i)
{
    float freq = exp2f(-ROPE_L2F * (float)i);
    float sn, cs; sincosf((float)t * freq, &sn, &cs);
    float a = v0*cs - v1*sn;
    float b = v0*sn + v1*cs;
    v0 = a; v1 = b;
}

// =====================================================================
// conversions (prep)
// =====================================================================
__global__ __launch_bounds__(256)
void convert_rows(const float* __restrict__ in, int ld, long total, int cols,
                  __half* __restrict__ oh, __half* __restrict__ ol)
{
    long i = (long)blockIdx.x * blockDim.x + threadIdx.x;
    long stride = (long)gridDim.x * blockDim.x;
    for (; i < total; i += stride) {
        long r = i / cols; int c = (int)(i - r*cols);
        float v = in[r*(long)ld + c];
        __half h = __float2half_rn(v);
        oh[i] = h;
        ol[i] = __float2half_rn(v - __half2float(h));
    }
}

__global__ __launch_bounds__(256)
void transpose_convert(const float* __restrict__ in, int N, int Kdim, int remap,
                       __half* __restrict__ oh, __half* __restrict__ ol)
{
    __shared__ float t[32][33];
    int tx = threadIdx.x & 31, ty = threadIdx.x >> 5;
    int k0 = blockIdx.x * 32, n0 = blockIdx.y * 32;
    #pragma unroll
    for (int i = 0; i < 4; i++) {
        int k = k0 + ty + i*8;
        int kr = remap ? ((k >> 6)*128 + (k & 63)) : k;
        int n = n0 + tx;
        t[ty + i*8][tx] = (n < N) ? in[(size_t)kr*N + n] : 0.f;
    }
    __syncthreads();
    #pragma unroll
    for (int i = 0; i < 4; i++) {
        int n = n0 + ty + i*8;
        int k = k0 + tx;
        float v = t[tx][ty + i*8];
        __half h = __float2half_rn(v);
        size_t o = (size_t)n*Kdim + k;
        oh[o] = h;
        ol[o] = __float2half_rn(v - __half2float(h));
    }
}

// Q: [bh][t][128] <- g_qf[(b*T+t)][h*128+d], rope applied to d>=64
__global__ __launch_bounds__(256)
void conv_q(const float* __restrict__ q, __half* __restrict__ oh, __half* __restrict__ ol)
{
    long i4 = (long)blockIdx.x*blockDim.x + threadIdx.x;
    if (i4 >= (long)BB*HH*TT*32) return;
    long i = i4*4;
    int d = (int)(i & 127); long r = i >> 7;
    int t = (int)(r & (TT-1)); int bh = (int)(r >> 11);
    int hh = bh & 15, bb = bh >> 4;
    float4 v = *(const float4*)&q[((size_t)(bb*TT + t))*2048 + hh*128 + d];
    if (d >= 64) {
        int i0 = (d - 64) >> 1;
        rope2(v.x, v.y, t, i0);
        rope2(v.z, v.w, t, i0 + 1);
    }
    __half h0 = __float2half_rn(v.x), h1 = __float2half_rn(v.y);
    __half h2 = __float2half_rn(v.z), h3 = __float2half_rn(v.w);
    *(__half2*)(oh + i)     = __halves2half2(h0, h1);
    *(__half2*)(oh + i + 2) = __halves2half2(h2, h3);
    *(__half2*)(ol + i)     = __halves2half2(__float2half_rn(v.x - __half2float(h0)),
                                             __float2half_rn(v.y - __half2float(h1)));
    *(__half2*)(ol + i + 2) = __halves2half2(__float2half_rn(v.z - __half2float(h2)),
                                             __float2half_rn(v.w - __half2float(h3)));
}

// k_rope: rope'd ckv cols 512..575 broadcast into Kh/Kl cols 64..127, all heads
__global__ __launch_bounds__(256)
void conv_krope(const float* __restrict__ ckv,
                __half* __restrict__ Kh, __half* __restrict__ Kl)
{
    int idx = blockIdx.x*blockDim.x + threadIdx.x;     // over BB*TT*32
    if (idx >= BB*TT*32) return;
    int i = idx & 31;
    int m = idx >> 5;
    int t = m & (TT-1), b = m >> 11;
    float2 v = *(const float2*)&ckv[(size_t)m*CKVW + LORA_ + 2*i];
    rope2(v.x, v.y, t, i);
    __half h0 = __float2half_rn(v.x), h1 = __float2half_rn(v.y);
    __half2 hi = __halves2half2(h0, h1);
    __half2 lo = __halves2half2(__float2half_rn(v.x - __half2float(h0)),
                                __float2half_rn(v.y - __half2float(h1)));
    size_t base = ((size_t)(b*HH)*TT + t)*128 + 64 + 2*i;
    #pragma unroll
    for (int h = 0; h < HH; h++) {
        *(__half2*)(Kh + base) = hi;
        *(__half2*)(Kl + base) = lo;
        base += (size_t)TT*128;
    }
}

// =====================================================================
// fp16-split HMMA GEMM. Epilogues are trig-free:
// MODE 0: fp32 C (o-proj).
// MODE 1: merged q-proj + ckv-proj. tiles 0..15 -> fp32 g_qf;
//         tiles 16..19 -> hi/lo split into a4 (latent);
//         tile  20     -> fp32 g_ckvf rope cols (512..575).
// MODE 2: kv-up -> hi/lo split into Kh/Kl cols 0..63 (== V).
// =====================================================================
#define STAGE_BYTES 32768
#define HG_STAGES   3
#define HG_SMEM     (STAGE_BYTES*HG_STAGES)

template<int MODE>
__global__ __launch_bounds__(256, 1)
void hgemm(const __half* __restrict__ Ah, const __half* __restrict__ Al,
           const __half* __restrict__ Bh, const __half* __restrict__ Bl,
           float* __restrict__ C, int K, int ldc, int Nvalid)
{
    extern __shared__ char smem[];
    const uint32_t sb = smem_u32(smem);
    const int tid  = threadIdx.x;
    const int wid  = tid >> 5, lane = tid & 31;
    const int row0 = blockIdx.y * 128;
    const int wm   = wid >> 1;
    const int wn   = wid & 1;

    const __half* BhP = Bh;
    const __half* BlP = Bl;
    int col0 = blockIdx.x * 128;
    if (MODE == 1 && blockIdx.x >= 16) {
        BhP = g_wah; BlP = g_wal;
        col0 = (blockIdx.x - 16) * 128;
    }

    int l_line[2], l_s8[2], l_r[2], l_c[2];
    #pragma unroll
    for (int j = 0; j < 2; j++) {
        int idx = tid + j*256;
        l_line[j] = idx >> 3;
        l_s8[j]   = idx & 7;
        int v     = l_s8[j] ^ (l_line[j] & 7);
        l_r[j]    = l_line[j]*2 + (v >> 2);
        l_c[j]    = v & 3;
    }

#define LOAD_STAGE(CH, ST) do { \
    uint32_t _base = sb + (uint32_t)(ST)*STAGE_BYTES; \
    _Pragma("unroll") \
    for (int _a = 0; _a < 4; _a++) { \
        const __half* _src = (_a == 0) ? Ah : (_a == 1) ? Al : (_a == 2) ? BhP : BlP; \
        int _rb = (_a < 2) ? row0 : col0; \
        _Pragma("unroll") \
        for (int _j = 0; _j < 2; _j++) { \
            const void* _g = _src + (size_t)(_rb + l_r[_j])*(size_t)K \
                             + (CH)*32 + l_c[_j]*8; \
            CP_ASYNC16(_base + _a*8192u + (uint32_t)(l_line[_j]*128 + l_s8[_j]*16), _g); \
        } \
    } \
    CP_COMMIT(); \
} while (0)

    float acc[2][8][4];
    #pragma unroll
    for (int mi = 0; mi < 2; mi++)
        #pragma unroll
        for (int nj = 0; nj < 8; nj++)
            #pragma unroll
            for (int e = 0; e < 4; e++) acc[mi][nj][e] = 0.f;

    const int nch = K >> 5;
    LOAD_STAGE(0, 0);
    LOAD_STAGE(1, 1);

    const int lr8 = (lane & 7) + ((lane >> 3) & 1)*8;
    const int chx = (lane >> 4);

    int st = 0;
    for (int ch = 0; ch < nch; ch++) {
        if (ch + 2 < nch) { CP_WAIT(1); } else { CP_WAIT(0); }
        __syncthreads();
        if (ch + 2 < nch) {
            int st2 = st + 2; if (st2 >= HG_STAGES) st2 -= HG_STAGES;
            LOAD_STAGE(ch + 2, st2);
        }

        const uint32_t base = sb + (uint32_t)st*STAGE_BYTES;
        #pragma unroll
        for (int kk = 0; kk < 2; kk++) {
            const int cc = kk*2 + chx;
            uint32_t a_h[2][4], a_l[2][4], b_h[4][4], b_l[4][4];

            #pragma unroll
            for (int mi = 0; mi < 2; mi++) {
                int r = wm*32 + mi*16 + lr8;
                uint32_t off = (uint32_t)((r >> 1)*128 +
                    (((cc | ((r & 1) << 2)) ^ ((r >> 1) & 7)) << 4));
                LDSM4(a_h[mi], base + off);
                LDSM4(a_l[mi], base + 8192u + off);
            }
            #pragma unroll
            for (int nb = 0; nb < 4; nb++) {
                int r = wn*64 + nb*16 + lr8;
                uint32_t off = (uint32_t)((r >> 1)*128 +
                    (((cc | ((r & 1) << 2)) ^ ((r >> 1) & 7)) << 4));
                LDSM4(b_h[nb], base + 16384u + off);
                LDSM4(b_l[nb], base + 24576u + off);
            }

            #pragma unroll
            for (int mi = 0; mi < 2; mi++)
                #pragma unroll
                for (int nb = 0; nb < 4; nb++)
                    #pragma unroll
                    for (int nn = 0; nn < 2; nn++) {
                        float* d = acc[mi][nb*2 + nn];
                        MMA16816(d, a_h[mi], b_h[nb][nn], b_h[nb][nn+2]);
                        MMA16816(d, a_h[mi], b_l[nb][nn], b_l[nb][nn+2]);
                        MMA16816(d, a_l[mi], b_h[nb][nn], b_h[nb][nn+2]);
                    }
        }
        st++; if (st >= HG_STAGES) st = 0;
    }

    // ---- epilogues (trig-free) ----
    #pragma unroll
    for (int mi = 0; mi < 2; mi++) {
        int m = row0 + wm*32 + mi*16 + (lane >> 2);
        #pragma unroll
        for (int nb = 0; nb < 4; nb++)
            #pragma unroll
            for (int nn = 0; nn < 2; nn++) {
                float* d = acc[mi][nb*2 + nn];
                int c = col0 + wn*64 + nb*16 + nn*8 + (lane & 3)*2;

                if (MODE == 0) {
                    if (c < Nvalid) {
                        *(float2*)&C[(size_t)m*ldc + c]       = make_float2(d[0], d[1]);
                        *(float2*)&C[(size_t)(m + 8)*ldc + c] = make_float2(d[2], d[3]);
                    }
                } else if (MODE == 1) {
                    if (blockIdx.x < 16) {
                        *(float2*)&g_qf[(size_t)m*2048 + c]       = make_float2(d[0], d[1]);
                        *(float2*)&g_qf[(size_t)(m + 8)*2048 + c] = make_float2(d[2], d[3]);
                    } else if (c < LORA_) {
                        sstore2(g_a4h, g_a4l, (size_t)m*512 + c,       d[0], d[1]);
                        sstore2(g_a4h, g_a4l, (size_t)(m + 8)*512 + c, d[2], d[3]);
                    } else if (c < CKVW) {
                        *(float2*)&g_ckvf[(size_t)m*CKVW + c]       = make_float2(d[0], d[1]);
                        *(float2*)&g_ckvf[(size_t)(m + 8)*CKVW + c] = make_float2(d[2], d[3]);
                    }
                } else { // MODE 2: kv-up -> Kh/Kl nope cols
                    int tA = m & (TT-1), bbA = m >> 11;
                    int h = c >> 6, dd = c & 63;
                    size_t b0 = ((size_t)(bbA*HH + h)*TT + tA)*128 + dd;
                    sstore2(g_Kh, g_Kl, b0, d[0], d[1]);
                    sstore2(g_Kh, g_Kl, b0 + (size_t)8*128, d[2], d[3]);
                }
            }
    }
}

// =====================================================================
// HMMA causal flash attention. V read from K tile (cols 0..63),
// PV uses V-hi only (error analysis: +~1.5e-4 RMS, budget-safe).
// smem: Qh[0,32K) Ql[32K,64K) + 2 stages of {Kh 16K, Kl 16K}.
// =====================================================================
#define ATM_SCALE 0.08838834764831845f
#define ATM_STAGE 32768
#define ATM_SMEM  (65536 + 2*ATM_STAGE)   /* 131072 */

__global__ __launch_bounds__(256, 1)
void attn_mma(const __half* __restrict__ Qh, const __half* __restrict__ Ql,
              const __half* __restrict__ Kh, const __half* __restrict__ Kl,
              __half* __restrict__ Oh, __half* __restrict__ Ol)
{
    extern __shared__ char smem[];
    const uint32_t sb = smem_u32(smem);
    const int tid  = threadIdx.x;
    const int wm   = tid >> 5, lane = tid & 31;
    const int qt   = (int)gridDim.x - 1 - (int)blockIdx.x;
    const int h    = blockIdx.y, b = blockIdx.z;
    const int bh   = b*HH + h;
    const int t0   = qt * 128;
    const size_t qrow  = ((size_t)bh*TT + t0)*128;
    const size_t krow0 = (size_t)bh*TT*128;

    for (int i = tid; i < 2048; i += 256) {
        int r = i >> 4, s = i & 15;
        uint32_t ph = (uint32_t)(r*256 + ((s ^ (r & 7)) << 4));
        *(uint4*)(smem + ph)         = *(const uint4*)(Qh + qrow + (size_t)r*128 + s*8);
        *(uint4*)(smem + 32768 + ph) = *(const uint4*)(Ql + qrow + (size_t)r*128 + s*8);
    }

    const int lr8 = (lane & 7) + ((lane >> 3) & 1)*8;
    const int chx = lane >> 4;

    float o_acc[8][4];
    #pragma unroll
    for (int j = 0; j < 8; j++)
        #pragma unroll
        for (int e = 0; e < 4; e++) o_acc[j][e] = 0.f;
    float m0 = -1e30f, m1 = -1e30f, l0 = 0.f, l1 = 0.f;

    const int nkt = 2*qt + 2;

#define ATM_PRE(KT, ST) do { \
    uint32_t bs = sb + 65536 + (uint32_t)(ST)*ATM_STAGE; \
    const __half* kh_ = Kh + krow0 + (size_t)(KT)*64*128; \
    const __half* kl_ = Kl + krow0 + (size_t)(KT)*64*128; \
    for (int i = tid; i < 1024; i += 256) { \
        int r = i >> 4, s = i & 15; \
        uint32_t ph = (uint32_t)(r*256 + ((s ^ (r & 7)) << 4)); \
        CP_ASYNC16(bs + ph,         kh_ + (size_t)r*128 + s*8); \
        CP_ASYNC16(bs + 16384 + ph, kl_ + (size_t)r*128 + s*8); \
    } \
    CP_COMMIT(); \
} while (0)

    ATM_PRE(0, 0);

    for (int kt = 0; kt < nkt; kt++) {
        const int st = kt & 1;
        CP_WAIT(0);
        __syncthreads();
        if (kt + 1 < nkt) ATM_PRE(kt + 1, st ^ 1);

        const uint32_t ks = sb + 65536 + (uint32_t)st*ATM_STAGE;

        float sacc[8][4];
        #pragma unroll
        for (int j = 0; j < 8; j++)
            #pragma unroll
            for (int e = 0; e < 4; e++) sacc[j][e] = 0.f;

        #pragma unroll
        for (int cc = 0; cc < 8; cc++) {
            uint32_t aqh[4], aql[4];
            {
                int r = wm*16 + lr8;
                int s = cc*2 + chx;
                uint32_t off = (uint32_t)(r*256 + ((s ^ (r & 7)) << 4));
                LDSM4(aqh, sb + off);
                LDSM4(aql, sb + 32768u + off);
            }
            #pragma unroll
            for (int nb = 0; nb < 4; nb++) {
                uint32_t bkh[4], bkl[4];
                int rn = nb*16 + lr8;
                int s = cc*2 + chx;
                uint32_t off = (uint32_t)(rn*256 + ((s ^ (rn & 7)) << 4));
                LDSM4(bkh, ks + off);
                LDSM4(bkl, ks + 16384u + off);
                MMA16816(sacc[nb*2],     aqh, bkh[0], bkh[2]);
                MMA16816(sacc[nb*2],     aqh, bkl[0], bkl[2]);
                MMA16816(sacc[nb*2],     aql, bkh[0], bkh[2]);
                MMA16816(sacc[nb*2 + 1], aqh, bkh[1], bkh[3]);
                MMA16816(sacc[nb*2 + 1], aqh, bkl[1], bkl[3]);
                MMA16816(sacc[nb*2 + 1], aql, bkh[1], bkh[3]);
            }
        }

        if (kt >= 2*qt) {
            int s0 = kt*64;
            int rb = t0 + wm*16 + (lane >> 2);
            #pragma unroll
            for (int j = 0; j < 8; j++) {
                int c0 = s0 + j*8 + (lane & 3)*2;
                if (c0     > rb)     sacc[j][0] = -3.0e38f;
                if (c0 + 1 > rb)     sacc[j][1] = -3.0e38f;
                if (c0     > rb + 8) sacc[j][2] = -3.0e38f;
                if (c0 + 1 > rb + 8) sacc[j][3] = -3.0e38f;
            }
        }

        float rm0 = -3.0e38f, rm1 = -3.0e38f;
        #pragma unroll
        for (int j = 0; j < 8; j++) {
            rm0 = fmaxf(rm0, fmaxf(sacc[j][0], sacc[j][1]));
            rm1 = fmaxf(rm1, fmaxf(sacc[j][2], sacc[j][3]));
        }
        rm0 = fmaxf(rm0, __shfl_xor_sync(0xffffffffu, rm0, 1));
        rm0 = fmaxf(rm0, __shfl_xor_sync(0xffffffffu, rm0, 2));
        rm1 = fmaxf(rm1, __shfl_xor_sync(0xffffffffu, rm1, 1));
        rm1 = fmaxf(rm1, __shfl_xor_sync(0xffffffffu, rm1, 2));
        float mn0 = fmaxf(m0, rm0), mn1 = fmaxf(m1, rm1);
        float f0  = __expf(ATM_SCALE*(m0 - mn0));
        float f1  = __expf(ATM_SCALE*(m1 - mn1));
        m0 = mn0; m1 = mn1;
        float rs0 = 0.f, rs1 = 0.f;
        #pragma unroll
        for (int j = 0; j < 8; j++) {
            sacc[j][0] = __expf(ATM_SCALE*(sacc[j][0] - mn0)); rs0 += sacc[j][0];
            sacc[j][1] = __expf(ATM_SCALE*(sacc[j][1] - mn0)); rs0 += sacc[j][1];
            sacc[j][2] = __expf(ATM_SCALE*(sacc[j][2] - mn1)); rs1 += sacc[j][2];
            sacc[j][3] = __expf(ATM_SCALE*(sacc[j][3] - mn1)); rs1 += sacc[j][3];
        }
        rs0 += __shfl_xor_sync(0xffffffffu, rs0, 1);
        rs0 += __shfl_xor_sync(0xffffffffu, rs0, 2);
        rs1 += __shfl_xor_sync(0xffffffffu, rs1, 1);
        rs1 += __shfl_xor_sync(0xffffffffu, rs1, 2);
        l0 = l0*f0 + rs0; l1 = l1*f1 + rs1;
        #pragma unroll
        for (int j = 0; j < 8; j++) {
            o_acc[j][0] *= f0; o_acc[j][1] *= f0;
            o_acc[j][2] *= f1; o_acc[j][3] *= f1;
        }

        uint32_t pf[4][4];
        #pragma unroll
        for (int kk = 0; kk < 4; kk++) {
            pf[kk][0] = h2u(__floats2half2_rn(sacc[2*kk][0],     sacc[2*kk][1]));
            pf[kk][1] = h2u(__floats2half2_rn(sacc[2*kk][2],     sacc[2*kk][3]));
            pf[kk][2] = h2u(__floats2half2_rn(sacc[2*kk + 1][0], sacc[2*kk + 1][1]));
            pf[kk][3] = h2u(__floats2half2_rn(sacc[2*kk + 1][2], sacc[2*kk + 1][3]));
        }

        // ---- O += P V  (V = K-hi cols 0..63 only) ----
        #pragma unroll
        for (int kk = 0; kk < 4; kk++) {
            #pragma unroll
            for (int nb = 0; nb < 4; nb++) {
                uint32_t bvh[4];
                int rv = kk*16 + lr8;
                int s = nb*2 + chx;
                uint32_t off = (uint32_t)(rv*256 + ((s ^ (rv & 7)) << 4));
                LDSM4T(bvh, ks + off);
                MMA16816(o_acc[nb*2],     pf[kk], bvh[0], bvh[1]);
                MMA16816(o_acc[nb*2 + 1], pf[kk], bvh[2], bvh[3]);
            }
        }
    }

    float il0 = 1.0f/l0, il1 = 1.0f/l1;
    int r0g = b*TT + t0 + wm*16 + (lane >> 2);
    size_t ob0 = (size_t)r0g*KVW + h*64;
    size_t ob1 = ob0 + (size_t)8*KVW;
    #pragma unroll
    for (int j = 0; j < 8; j++) {
        int d = j*8 + (lane & 3)*2;
        sstore2(Oh, Ol, ob0 + d, o_acc[j][0]*il0, o_acc[j][1]*il0);
        sstore2(Oh, Ol, ob1 + d, o_acc[j][2]*il1, o_acc[j][3]*il1);
    }
}

// =====================================================================
// launch  (ordered so hgemm<1> is our launch #3 -> ncu's captured index)
// =====================================================================
extern "C" void kernel_launch(void* const* d_in, const int* in_sizes, int n_in,
                              void* d_out, int out_size)
{
    const float* x    = (const float*)d_in[0];
    const float* Wq   = (const float*)d_in[1];
    const float* Wkva = (const float*)d_in[2];
    const float* Wkvb = (const float*)d_in[3];
    const float* Wo   = (const float*)d_in[4];
    float* out        = (float*)d_out;

    float *qf, *ckvf;
    cudaGetSymbolAddress((void**)&qf,   g_qf);
    cudaGetSymbolAddress((void**)&ckvf, g_ckvf);

    __half *xh,*xl,*wqh,*wql,*wah,*wal,*wbh,*wbl,*woh,*wol,*a4h,*a4l,*a6h,*a6l;
    __half *Qh,*Ql,*Kh,*Kl;
    cudaGetSymbolAddress((void**)&xh,  g_xh);  cudaGetSymbolAddress((void**)&xl,  g_xl);
    cudaGetSymbolAddress((void**)&wqh, g_wqh); cudaGetSymbolAddress((void**)&wql, g_wql);
    cudaGetSymbolAddress((void**)&wah, g_wah); cudaGetSymbolAddress((void**)&wal, g_wal);
    cudaGetSymbolAddress((void**)&wbh, g_wbh); cudaGetSymbolAddress((void**)&wbl, g_wbl);
    cudaGetSymbolAddress((void**)&woh, g_woh); cudaGetSymbolAddress((void**)&wol, g_wol);
    cudaGetSymbolAddress((void**)&a4h, g_a4h); cudaGetSymbolAddress((void**)&a4l, g_a4l);
    cudaGetSymbolAddress((void**)&a6h, g_a6h); cudaGetSymbolAddress((void**)&a6l, g_a6l);
    cudaGetSymbolAddress((void**)&Qh,  g_Qh);  cudaGetSymbolAddress((void**)&Ql,  g_Ql);
    cudaGetSymbolAddress((void**)&Kh,  g_Kh);  cudaGetSymbolAddress((void**)&Kl,  g_Kl);

    cudaFuncSetAttribute(hgemm<0>, cudaFuncAttributeMaxDynamicSharedMemorySize, HG_SMEM);
    cudaFuncSetAttribute(hgemm<1>, cudaFuncAttributeMaxDynamicSharedMemorySize, HG_SMEM);
    cudaFuncSetAttribute(hgemm<2>, cudaFuncAttributeMaxDynamicSharedMemorySize, HG_SMEM);
    cudaFuncSetAttribute(attn_mma, cudaFuncAttributeMaxDynamicSharedMemorySize, ATM_SMEM);

    dim3 blk(256);

    // [0] x -> hi/lo
    convert_rows<<<4096, blk>>>(x, CCH, (long)MTOT*CCH, CCH, xh, xl);
    // [1][2] weights needed by hgemm<1>
    transpose_convert<<<dim3(2048/32, 2048/32), blk>>>(Wq,   2048, 2048, 0, wqh, wql);
    transpose_convert<<<dim3(2048/32, NAPAD/32), blk>>>(Wkva, CKVW, 2048, 0, wah, wal);

    // [3] merged q-proj + ckv-proj (-> qf fp32, a4 split, ckvf rope cols)
    hgemm<1><<<dim3(21, MTOT/128), blk, HG_SMEM>>>(xh, xl, wqh, wql, nullptr,
        2048, 0, 0);

    // [4][5] remaining weight prep
    transpose_convert<<<dim3(512/32,  1024/32), blk>>>(Wkvb, 1024, 512,  0, wbh, wbl);
    transpose_convert<<<dim3(1024/32, 2048/32), blk>>>(Wo,   2048, 1024, 1, woh, wol);

    // [6] k_rope: rope + broadcast into Kh/Kl cols 64..127
    conv_krope<<<(BB*TT*32 + 255)/256, blk>>>(ckvf, Kh, Kl);

    // [7] kv-up: latent @ Wkvb -> Kh/Kl cols 0..63 (== V)
    hgemm<2><<<dim3(8, MTOT/128), blk, HG_SMEM>>>(a4h, a4l, wbh, wbl, nullptr,
        512, 0, 0);

    // [8] q: rope + hi/lo split -> Qh/Ql
    conv_q<<<8192, blk>>>(qf, Qh, Ql);

    // [9] attention -> a6h/a6l (o-proj operand)
    attn_mma<<<dim3(TT/128, HH, BB), blk, ATM_SMEM>>>(Qh, Ql, Kh, Kl, a6h, a6l);

    // [10] out = y_nope @ Wo[nope rows]
    hgemm<0><<<dim3(16, MTOT/128), blk, HG_SMEM>>>(a6h, a6l, woh, wol, out,
        1024, 2048, 2048);
}

// round 14
// speedup vs baseline: 1.7790x; 1.0878x over previous
#include <cuda_runtime.h>
#include <cuda_fp16.h>
#include <stdint.h>
#include <math.h>
#include <float.h>

// ---------------- problem constants ----------------
#define BB    2
#define TT    2048
#define CCH   2048
#define HH    16
#define HDD   128
#define LORA_ 512
#define RDIM  64
#define NDIM  64
#define MTOT  (BB*TT)        /* 4096 */
#define CKVW  (LORA_+RDIM)   /* 576  */
#define KVW   (HH*NDIM)      /* 1024 */
#define NAPAD 640

// ---------------- fp32 scratch ----------------
__device__ float g_qf  [(size_t)MTOT * 2048];   // q projection (pre-rope)
__device__ float g_ckvf[(size_t)MTOT * CKVW];   // only cols 512..575 used (k_rope)

// ---------------- fp16 split (hi/lo) buffers ----------------
__device__ __align__(128) __half g_xh [(size_t)MTOT*CCH],  g_xl [(size_t)MTOT*CCH];
__device__ __align__(128) __half g_wqh[(size_t)2048*2048], g_wql[(size_t)2048*2048];
__device__ __align__(128) __half g_wah[(size_t)NAPAD*2048],g_wal[(size_t)NAPAD*2048];
__device__ __align__(128) __half g_wbh[(size_t)1024*512],  g_wbl[(size_t)1024*512];
__device__ __align__(128) __half g_woh[(size_t)2048*1024], g_wol[(size_t)2048*1024];
__device__ __align__(128) __half g_a4h[(size_t)MTOT*512],  g_a4l[(size_t)MTOT*512];
__device__ __align__(128) __half g_a6h[(size_t)MTOT*1024], g_a6l[(size_t)MTOT*1024];
// attention operands [bh][t][d]; V == K[:, 0:64]
__device__ __align__(128) __half g_Qh[(size_t)BB*HH*TT*128], g_Ql[(size_t)BB*HH*TT*128];
__device__ __align__(128) __half g_Kh[(size_t)BB*HH*TT*128], g_Kl[(size_t)BB*HH*TT*128];

// =====================================================================
// PTX helpers (baseline sm_80+ — compile at compute_103)
// =====================================================================
__device__ __forceinline__ uint32_t smem_u32(const void* p) {
    uint32_t a;
    asm("{ .reg .u64 t; cvta.to.shared.u64 t, %1; cvt.u32.u64 %0, t; }" : "=r"(a) : "l"(p));
    return a;
}
#define CP_ASYNC16(dst, src) \
    asm volatile("cp.async.cg.shared.global [%0], [%1], 16;" :: "r"(dst), "l"(src))
#define CP_COMMIT() asm volatile("cp.async.commit_group;" ::: "memory")
#define CP_WAIT(n)  asm volatile("cp.async.wait_group %0;" :: "n"(n) : "memory")

#define LDSM4(R, addr) \
    asm volatile("ldmatrix.sync.aligned.m8n8.x4.shared.b16 {%0,%1,%2,%3}, [%4];" \
        : "=r"((R)[0]), "=r"((R)[1]), "=r"((R)[2]), "=r"((R)[3]) : "r"(addr))
#define LDSM4T(R, addr) \
    asm volatile("ldmatrix.sync.aligned.m8n8.x4.trans.shared.b16 {%0,%1,%2,%3}, [%4];" \
        : "=r"((R)[0]), "=r"((R)[1]), "=r"((R)[2]), "=r"((R)[3]) : "r"(addr))

#define MMA16816(D, A, B0, B1) \
    asm volatile("mma.sync.aligned.m16n8k16.row.col.f32.f16.f16.f32 " \
        "{%0,%1,%2,%3}, {%4,%5,%6,%7}, {%8,%9}, {%0,%1,%2,%3};" \
        : "+f"((D)[0]), "+f"((D)[1]), "+f"((D)[2]), "+f"((D)[3]) \
        : "r"((A)[0]), "r"((A)[1]), "r"((A)[2]), "r"((A)[3]), "r"(B0), "r"(B1))

__device__ __forceinline__ uint32_t h2u(__half2 v) { return *(uint32_t*)&v; }

// hi/lo split store of a (v0,v1) pair
__device__ __forceinline__ void sstore2(__half* __restrict__ oh, __half* __restrict__ ol,
                                        size_t idx, float v0, float v1)
{
    __half h0 = __float2half_rn(v0), h1 = __float2half_rn(v1);
    *(__half2*)(oh + idx) = __halves2half2(h0, h1);
    *(__half2*)(ol + idx) = __halves2half2(__float2half_rn(v0 - __half2float(h0)),
                                           __float2half_rn(v1 - __half2float(h1)));
}

// RoPE: freq_i = theta^(-i/32) = 2^(-i*log2(1e5)/32)
#define ROPE_L2F 0.5190512648261504f
__device__ __forceinline__ void rope2(float& v0, float& v1, int t, int i)
{
    float freq = exp2f(-ROPE_L2F * (float)i);
    float sn, cs; sincosf((float)t * freq, &sn, &cs);
    float a = v0*cs - v1*sn;
    float b = v0*sn + v1*cs;
    v0 = a; v1 = b;
}

// =====================================================================
// conversions (prep)
// =====================================================================
__global__ __launch_bounds__(256)
void convert_rows(const float* __restrict__ in, int ld, long total, int cols,
                  __half* __restrict__ oh, __half* __restrict__ ol)
{
    long i = (long)blockIdx.x * blockDim.x + threadIdx.x;
    long stride = (long)gridDim.x * blockDim.x;
    for (; i < total; i += stride) {
        long r = i / cols; int c = (int)(i - r*cols);
        float v = in[r*(long)ld + c];
        __half h = __float2half_rn(v);
        oh[i] = h;
        ol[i] = __float2half_rn(v - __half2float(h));
    }
}

__global__ __launch_bounds__(256)
void transpose_convert(const float* __restrict__ in, int N, int Kdim, int remap,
                       __half* __restrict__ oh, __half* __restrict__ ol)
{
    __shared__ float t[32][33];
    int tx = threadIdx.x & 31, ty = threadIdx.x >> 5;
    int k0 = blockIdx.x * 32, n0 = blockIdx.y * 32;
    #pragma unroll
    for (int i = 0; i < 4; i++) {
        int k = k0 + ty + i*8;
        int kr = remap ? ((k >> 6)*128 + (k & 63)) : k;
        int n = n0 + tx;
        t[ty + i*8][tx] = (n < N) ? in[(size_t)kr*N + n] : 0.f;
    }
    __syncthreads();
    #pragma unroll
    for (int i = 0; i < 4; i++) {
        int n = n0 + ty + i*8;
        int k = k0 + tx;
        float v = t[tx][ty + i*8];
        __half h = __float2half_rn(v);
        size_t o = (size_t)n*Kdim + k;
        oh[o] = h;
        ol[o] = __float2half_rn(v - __half2float(h));
    }
}

// Q: [bh][t][128] <- g_qf[(b*T+t)][h*128+d], rope applied to d>=64
__global__ __launch_bounds__(256)
void conv_q(const float* __restrict__ q, __half* __restrict__ oh, __half* __restrict__ ol)
{
    long i4 = (long)blockIdx.x*blockDim.x + threadIdx.x;
    if (i4 >= (long)BB*HH*TT*32) return;
    long i = i4*4;
    int d = (int)(i & 127); long r = i >> 7;
    int t = (int)(r & (TT-1)); int bh = (int)(r >> 11);
    int hh = bh & 15, bb = bh >> 4;
    float4 v = *(const float4*)&q[((size_t)(bb*TT + t))*2048 + hh*128 + d];
    if (d >= 64) {
        int i0 = (d - 64) >> 1;
        rope2(v.x, v.y, t, i0);
        rope2(v.z, v.w, t, i0 + 1);
    }
    __half h0 = __float2half_rn(v.x), h1 = __float2half_rn(v.y);
    __half h2 = __float2half_rn(v.z), h3 = __float2half_rn(v.w);
    *(__half2*)(oh + i)     = __halves2half2(h0, h1);
    *(__half2*)(oh + i + 2) = __halves2half2(h2, h3);
    *(__half2*)(ol + i)     = __halves2half2(__float2half_rn(v.x - __half2float(h0)),
                                             __float2half_rn(v.y - __half2float(h1)));
    *(__half2*)(ol + i + 2) = __halves2half2(__float2half_rn(v.z - __half2float(h2)),
                                             __float2half_rn(v.w - __half2float(h3)));
}

// k_rope: rope'd ckv cols 512..575 broadcast into Kh/Kl cols 64..127, all heads
__global__ __launch_bounds__(256)
void conv_krope(const float* __restrict__ ckv,
                __half* __restrict__ Kh, __half* __restrict__ Kl)
{
    int idx = blockIdx.x*blockDim.x + threadIdx.x;     // over BB*TT*32
    if (idx >= BB*TT*32) return;
    int i = idx & 31;
    int m = idx >> 5;
    int t = m & (TT-1), b = m >> 11;
    float2 v = *(const float2*)&ckv[(size_t)m*CKVW + LORA_ + 2*i];
    rope2(v.x, v.y, t, i);
    __half h0 = __float2half_rn(v.x), h1 = __float2half_rn(v.y);
    __half2 hi = __halves2half2(h0, h1);
    __half2 lo = __halves2half2(__float2half_rn(v.x - __half2float(h0)),
                                __float2half_rn(v.y - __half2float(h1)));
    size_t base = ((size_t)(b*HH)*TT + t)*128 + 64 + 2*i;
    #pragma unroll
    for (int h = 0; h < HH; h++) {
        *(__half2*)(Kh + base) = hi;
        *(__half2*)(Kl + base) = lo;
        base += (size_t)TT*128;
    }
}

// =====================================================================
// fp16-split HMMA GEMM. 2 CTAs/SM (regs capped at 128 via launch bounds;
// B fragments loaded per-nb to shrink the live set). Epilogues trig-free:
// MODE 0: fp32 C (o-proj).
// MODE 1: merged q-proj + ckv-proj. tiles 0..15 -> fp32 g_qf;
//         tiles 16..19 -> hi/lo split into a4 (latent);
//         tile  20     -> fp32 g_ckvf rope cols (512..575).
// MODE 2: kv-up -> hi/lo split into Kh/Kl cols 0..63 (== V).
// =====================================================================
#define STAGE_BYTES 32768
#define HG_STAGES   3
#define HG_SMEM     (STAGE_BYTES*HG_STAGES)

template<int MODE>
__global__ __launch_bounds__(256, 2)
void hgemm(const __half* __restrict__ Ah, const __half* __restrict__ Al,
           const __half* __restrict__ Bh, const __half* __restrict__ Bl,
           float* __restrict__ C, int K, int ldc, int Nvalid)
{
    extern __shared__ char smem[];
    const uint32_t sb = smem_u32(smem);
    const int tid  = threadIdx.x;
    const int wid  = tid >> 5, lane = tid & 31;
    const int row0 = blockIdx.y * 128;
    const int wm   = wid >> 1;
    const int wn   = wid & 1;

    const __half* BhP = Bh;
    const __half* BlP = Bl;
    int col0 = blockIdx.x * 128;
    if (MODE == 1 && blockIdx.x >= 16) {
        BhP = g_wah; BlP = g_wal;
        col0 = (blockIdx.x - 16) * 128;
    }

    int l_line[2], l_s8[2], l_r[2], l_c[2];
    #pragma unroll
    for (int j = 0; j < 2; j++) {
        int idx = tid + j*256;
        l_line[j] = idx >> 3;
        l_s8[j]   = idx & 7;
        int v     = l_s8[j] ^ (l_line[j] & 7);
        l_r[j]    = l_line[j]*2 + (v >> 2);
        l_c[j]    = v & 3;
    }

#define LOAD_STAGE(CH, ST) do { \
    uint32_t _base = sb + (uint32_t)(ST)*STAGE_BYTES; \
    _Pragma("unroll") \
    for (int _a = 0; _a < 4; _a++) { \
        const __half* _src = (_a == 0) ? Ah : (_a == 1) ? Al : (_a == 2) ? BhP : BlP; \
        int _rb = (_a < 2) ? row0 : col0; \
        _Pragma("unroll") \
        for (int _j = 0; _j < 2; _j++) { \
            const void* _g = _src + (size_t)(_rb + l_r[_j])*(size_t)K \
                             + (CH)*32 + l_c[_j]*8; \
            CP_ASYNC16(_base + _a*8192u + (uint32_t)(l_line[_j]*128 + l_s8[_j]*16), _g); \
        } \
    } \
    CP_COMMIT(); \
} while (0)

    float acc[2][8][4];
    #pragma unroll
    for (int mi = 0; mi < 2; mi++)
        #pragma unroll
        for (int nj = 0; nj < 8; nj++)
            #pragma unroll
            for (int e = 0; e < 4; e++) acc[mi][nj][e] = 0.f;

    const int nch = K >> 5;
    LOAD_STAGE(0, 0);
    LOAD_STAGE(1, 1);

    const int lr8 = (lane & 7) + ((lane >> 3) & 1)*8;
    const int chx = (lane >> 4);

    int st = 0;
    for (int ch = 0; ch < nch; ch++) {
        if (ch + 2 < nch) { CP_WAIT(1); } else { CP_WAIT(0); }
        __syncthreads();
        if (ch + 2 < nch) {
            int st2 = st + 2; if (st2 >= HG_STAGES) st2 -= HG_STAGES;
            LOAD_STAGE(ch + 2, st2);
        }

        const uint32_t base = sb + (uint32_t)st*STAGE_BYTES;
        #pragma unroll
        for (int kk = 0; kk < 2; kk++) {
            const int cc = kk*2 + chx;
            uint32_t a_h[2][4], a_l[2][4];

            #pragma unroll
            for (int mi = 0; mi < 2; mi++) {
                int r = wm*32 + mi*16 + lr8;
                uint32_t off = (uint32_t)((r >> 1)*128 +
                    (((cc | ((r & 1) << 2)) ^ ((r >> 1) & 7)) << 4));
                LDSM4(a_h[mi], base + off);
                LDSM4(a_l[mi], base + 8192u + off);
            }
            // B fragments loaded per-nb: live b-regs 8 instead of 32.
            #pragma unroll
            for (int nb = 0; nb < 4; nb++) {
                uint32_t b_h[4], b_l[4];
                int r = wn*64 + nb*16 + lr8;
                uint32_t off = (uint32_t)((r >> 1)*128 +
                    (((cc | ((r & 1) << 2)) ^ ((r >> 1) & 7)) << 4));
                LDSM4(b_h, base + 16384u + off);
                LDSM4(b_l, base + 24576u + off);

                #pragma unroll
                for (int mi = 0; mi < 2; mi++)
                    #pragma unroll
                    for (int nn = 0; nn < 2; nn++) {
                        float* d = acc[mi][nb*2 + nn];
                        MMA16816(d, a_h[mi], b_h[nn], b_h[nn+2]);
                        MMA16816(d, a_h[mi], b_l[nn], b_l[nn+2]);
                        MMA16816(d, a_l[mi], b_h[nn], b_h[nn+2]);
                    }
            }
        }
        st++; if (st >= HG_STAGES) st = 0;
    }

    // ---- epilogues (trig-free) ----
    #pragma unroll
    for (int mi = 0; mi < 2; mi++) {
        int m = row0 + wm*32 + mi*16 + (lane >> 2);
        #pragma unroll
        for (int nb = 0; nb < 4; nb++)
            #pragma unroll
            for (int nn = 0; nn < 2; nn++) {
                float* d = acc[mi][nb*2 + nn];
                int c = col0 + wn*64 + nb*16 + nn*8 + (lane & 3)*2;

                if (MODE == 0) {
                    if (c < Nvalid) {
                        *(float2*)&C[(size_t)m*ldc + c]       = make_float2(d[0], d[1]);
                        *(float2*)&C[(size_t)(m + 8)*ldc + c] = make_float2(d[2], d[3]);
                    }
                } else if (MODE == 1) {
                    if (blockIdx.x < 16) {
                        *(float2*)&g_qf[(size_t)m*2048 + c]       = make_float2(d[0], d[1]);
                        *(float2*)&g_qf[(size_t)(m + 8)*2048 + c] = make_float2(d[2], d[3]);
                    } else if (c < LORA_) {
                        sstore2(g_a4h, g_a4l, (size_t)m*512 + c,       d[0], d[1]);
                        sstore2(g_a4h, g_a4l, (size_t)(m + 8)*512 + c, d[2], d[3]);
                    } else if (c < CKVW) {
                        *(float2*)&g_ckvf[(size_t)m*CKVW + c]       = make_float2(d[0], d[1]);
                        *(float2*)&g_ckvf[(size_t)(m + 8)*CKVW + c] = make_float2(d[2], d[3]);
                    }
                } else { // MODE 2: kv-up -> Kh/Kl nope cols
                    int tA = m & (TT-1), bbA = m >> 11;
                    int h = c >> 6, dd = c & 63;
                    size_t b0 = ((size_t)(bbA*HH + h)*TT + tA)*128 + dd;
                    sstore2(g_Kh, g_Kl, b0, d[0], d[1]);
                    sstore2(g_Kh, g_Kl, b0 + (size_t)8*128, d[2], d[3]);
                }
            }
    }
}

// =====================================================================
// HMMA causal flash attention. V read from K tile (cols 0..63),
// PV uses V-hi only. smem: Qh/Ql 64K + 2 stages {Kh 16K, Kl 16K}.
// =====================================================================
#define ATM_SCALE 0.08838834764831845f
#define ATM_STAGE 32768
#define ATM_SMEM  (65536 + 2*ATM_STAGE)   /* 131072 */

__global__ __launch_bounds__(256, 1)
void attn_mma(const __half* __restrict__ Qh, const __half* __restrict__ Ql,
              const __half* __restrict__ Kh, const __half* __restrict__ Kl,
              __half* __restrict__ Oh, __half* __restrict__ Ol)
{
    extern __shared__ char smem[];
    const uint32_t sb = smem_u32(smem);
    const int tid  = threadIdx.x;
    const int wm   = tid >> 5, lane = tid & 31;
    const int qt   = (int)gridDim.x - 1 - (int)blockIdx.x;
    const int h    = blockIdx.y, b = blockIdx.z;
    const int bh   = b*HH + h;
    const int t0   = qt * 128;
    const size_t qrow  = ((size_t)bh*TT + t0)*128;
    const size_t krow0 = (size_t)bh*TT*128;

    for (int i = tid; i < 2048; i += 256) {
        int r = i >> 4, s = i & 15;
        uint32_t ph = (uint32_t)(r*256 + ((s ^ (r & 7)) << 4));
        *(uint4*)(smem + ph)         = *(const uint4*)(Qh + qrow + (size_t)r*128 + s*8);
        *(uint4*)(smem + 32768 + ph) = *(const uint4*)(Ql + qrow + (size_t)r*128 + s*8);
    }

    const int lr8 = (lane & 7) + ((lane >> 3) & 1)*8;
    const int chx = lane >> 4;

    float o_acc[8][4];
    #pragma unroll
    for (int j = 0; j < 8; j++)
        #pragma unroll
        for (int e = 0; e < 4; e++) o_acc[j][e] = 0.f;
    float m0 = -1e30f, m1 = -1e30f, l0 = 0.f, l1 = 0.f;

    const int nkt = 2*qt + 2;

#define ATM_PRE(KT, ST) do { \
    uint32_t bs = sb + 65536 + (uint32_t)(ST)*ATM_STAGE; \
    const __half* kh_ = Kh + krow0 + (size_t)(KT)*64*128; \
    const __half* kl_ = Kl + krow0 + (size_t)(KT)*64*128; \
    for (int i = tid; i < 1024; i += 256) { \
        int r = i >> 4, s = i & 15; \
        uint32_t ph = (uint32_t)(r*256 + ((s ^ (r & 7)) << 4)); \
        CP_ASYNC16(bs + ph,         kh_ + (size_t)r*128 + s*8); \
        CP_ASYNC16(bs + 16384 + ph, kl_ + (size_t)r*128 + s*8); \
    } \
    CP_COMMIT(); \
} while (0)

    ATM_PRE(0, 0);

    for (int kt = 0; kt < nkt; kt++) {
        const int st = kt & 1;
        CP_WAIT(0);
        __syncthreads();
        if (kt + 1 < nkt) ATM_PRE(kt + 1, st ^ 1);

        const uint32_t ks = sb + 65536 + (uint32_t)st*ATM_STAGE;

        float sacc[8][4];
        #pragma unroll
        for (int j = 0; j < 8; j++)
            #pragma unroll
            for (int e = 0; e < 4; e++) sacc[j][e] = 0.f;

        #pragma unroll
        for (int cc = 0; cc < 8; cc++) {
            uint32_t aqh[4], aql[4];
            {
                int r = wm*16 + lr8;
                int s = cc*2 + chx;
                uint32_t off = (uint32_t)(r*256 + ((s ^ (r & 7)) << 4));
                LDSM4(aqh, sb + off);
                LDSM4(aql, sb + 32768u + off);
            }
            #pragma unroll
            for (int nb = 0; nb < 4; nb++) {
                uint32_t bkh[4], bkl[4];
                int rn = nb*16 + lr8;
                int s = cc*2 + chx;
                uint32_t off = (uint32_t)(rn*256 + ((s ^ (rn & 7)) << 4));
                LDSM4(bkh, ks + off);
                LDSM4(bkl, ks + 16384u + off);
                MMA16816(sacc[nb*2],     aqh, bkh[0], bkh[2]);
                MMA16816(sacc[nb*2],     aqh, bkl[0], bkl[2]);
                MMA16816(sacc[nb*2],     aql, bkh[0], bkh[2]);
                MMA16816(sacc[nb*2 + 1], aqh, bkh[1], bkh[3]);
                MMA16816(sacc[nb*2 + 1], aqh, bkl[1], bkl[3]);
                MMA16816(sacc[nb*2 + 1], aql, bkh[1], bkh[3]);
            }
        }

        if (kt >= 2*qt) {
            int s0 = kt*64;
            int rb = t0 + wm*16 + (lane >> 2);
            #pragma unroll
            for (int j = 0; j < 8; j++) {
                int c0 = s0 + j*8 + (lane & 3)*2;
                if (c0     > rb)     sacc[j][0] = -3.0e38f;
                if (c0 + 1 > rb)     sacc[j][1] = -3.0e38f;
                if (c0     > rb + 8) sacc[j][2] = -3.0e38f;
                if (c0 + 1 > rb + 8) sacc[j][3] = -3.0e38f;
            }
        }

        float rm0 = -3.0e38f, rm1 = -3.0e38f;
        #pragma unroll
        for (int j = 0; j < 8; j++) {
            rm0 = fmaxf(rm0, fmaxf(sacc[j][0], sacc[j][1]));
            rm1 = fmaxf(rm1, fmaxf(sacc[j][2], sacc[j][3]));
        }
        rm0 = fmaxf(rm0, __shfl_xor_sync(0xffffffffu, rm0, 1));
        rm0 = fmaxf(rm0, __shfl_xor_sync(0xffffffffu, rm0, 2));
        rm1 = fmaxf(rm1, __shfl_xor_sync(0xffffffffu, rm1, 1));
        rm1 = fmaxf(rm1, __shfl_xor_sync(0xffffffffu, rm1, 2));
        float mn0 = fmaxf(m0, rm0), mn1 = fmaxf(m1, rm1);
        float f0  = __expf(ATM_SCALE*(m0 - mn0));
        float f1  = __expf(ATM_SCALE*(m1 - mn1));
        m0 = mn0; m1 = mn1;
        float rs0 = 0.f, rs1 = 0.f;
        #pragma unroll
        for (int j = 0; j < 8; j++) {
            sacc[j][0] = __expf(ATM_SCALE*(sacc[j][0] - mn0)); rs0 += sacc[j][0];
            sacc[j][1] = __expf(ATM_SCALE*(sacc[j][1] - mn0)); rs0 += sacc[j][1];
            sacc[j][2] = __expf(ATM_SCALE*(sacc[j][2] - mn1)); rs1 += sacc[j][2];
            sacc[j][3] = __expf(ATM_SCALE*(sacc[j][3] - mn1)); rs1 += sacc[j][3];
        }
        rs0 += __shfl_xor_sync(0xffffffffu, rs0, 1);
        rs0 += __shfl_xor_sync(0xffffffffu, rs0, 2);
        rs1 += __shfl_xor_sync(0xffffffffu, rs1, 1);
        rs1 += __shfl_xor_sync(0xffffffffu, rs1, 2);
        l0 = l0*f0 + rs0; l1 = l1*f1 + rs1;
        #pragma unroll
        for (int j = 0; j < 8; j++) {
            o_acc[j][0] *= f0; o_acc[j][1] *= f0;
            o_acc[j][2] *= f1; o_acc[j][3] *= f1;
        }

        uint32_t pf[4][4];
        #pragma unroll
        for (int kk = 0; kk < 4; kk++) {
            pf[kk][0] = h2u(__floats2half2_rn(sacc[2*kk][0],     sacc[2*kk][1]));
            pf[kk][1] = h2u(__floats2half2_rn(sacc[2*kk][2],     sacc[2*kk][3]));
            pf[kk][2] = h2u(__floats2half2_rn(sacc[2*kk + 1][0], sacc[2*kk + 1][1]));
            pf[kk][3] = h2u(__floats2half2_rn(sacc[2*kk + 1][2], sacc[2*kk + 1][3]));
        }

        // ---- O += P V  (V = K-hi cols 0..63 only) ----
        #pragma unroll
        for (int kk = 0; kk < 4; kk++) {
            #pragma unroll
            for (int nb = 0; nb < 4; nb++) {
                uint32_t bvh[4];
                int rv = kk*16 + lr8;
                int s = nb*2 + chx;
                uint32_t off = (uint32_t)(rv*256 + ((s ^ (rv & 7)) << 4));
                LDSM4T(bvh, ks + off);
                MMA16816(o_acc[nb*2],     pf[kk], bvh[0], bvh[1]);
                MMA16816(o_acc[nb*2 + 1], pf[kk], bvh[2], bvh[3]);
            }
        }
    }

    float il0 = 1.0f/l0, il1 = 1.0f/l1;
    int r0g = b*TT + t0 + wm*16 + (lane >> 2);
    size_t ob0 = (size_t)r0g*KVW + h*64;
    size_t ob1 = ob0 + (size_t)8*KVW;
    #pragma unroll
    for (int j = 0; j < 8; j++) {
        int d = j*8 + (lane & 3)*2;
        sstore2(Oh, Ol, ob0 + d, o_acc[j][0]*il0, o_acc[j][1]*il0);
        sstore2(Oh, Ol, ob1 + d, o_acc[j][2]*il1, o_acc[j][3]*il1);
    }
}

// =====================================================================
// launch  (hgemm<1> at our index 3 for ncu capture)
// =====================================================================
extern "C" void kernel_launch(void* const* d_in, const int* in_sizes, int n_in,
                              void* d_out, int out_size)
{
    const float* x    = (const float*)d_in[0];
    const float* Wq   = (const float*)d_in[1];
    const float* Wkva = (const float*)d_in[2];
    const float* Wkvb = (const float*)d_in[3];
    const float* Wo   = (const float*)d_in[4];
    float* out        = (float*)d_out;

    float *qf, *ckvf;
    cudaGetSymbolAddress((void**)&qf,   g_qf);
    cudaGetSymbolAddress((void**)&ckvf, g_ckvf);

    __half *xh,*xl,*wqh,*wql,*wah,*wal,*wbh,*wbl,*woh,*wol,*a4h,*a4l,*a6h,*a6l;
    __half *Qh,*Ql,*Kh,*Kl;
    cudaGetSymbolAddress((void**)&xh,  g_xh);  cudaGetSymbolAddress((void**)&xl,  g_xl);
    cudaGetSymbolAddress((void**)&wqh, g_wqh); cudaGetSymbolAddress((void**)&wql, g_wql);
    cudaGetSymbolAddress((void**)&wah, g_wah); cudaGetSymbolAddress((void**)&wal, g_wal);
    cudaGetSymbolAddress((void**)&wbh, g_wbh); cudaGetSymbolAddress((void**)&wbl, g_wbl);
    cudaGetSymbolAddress((void**)&woh, g_woh); cudaGetSymbolAddress((void**)&wol, g_wol);
    cudaGetSymbolAddress((void**)&a4h, g_a4h); cudaGetSymbolAddress((void**)&a4l, g_a4l);
    cudaGetSymbolAddress((void**)&a6h, g_a6h); cudaGetSymbolAddress((void**)&a6l, g_a6l);
    cudaGetSymbolAddress((void**)&Qh,  g_Qh);  cudaGetSymbolAddress((void**)&Ql,  g_Ql);
    cudaGetSymbolAddress((void**)&Kh,  g_Kh);  cudaGetSymbolAddress((void**)&Kl,  g_Kl);

    cudaFuncSetAttribute(hgemm<0>, cudaFuncAttributeMaxDynamicSharedMemorySize, HG_SMEM);
    cudaFuncSetAttribute(hgemm<1>, cudaFuncAttributeMaxDynamicSharedMemorySize, HG_SMEM);
    cudaFuncSetAttribute(hgemm<2>, cudaFuncAttributeMaxDynamicSharedMemorySize, HG_SMEM);
    cudaFuncSetAttribute(attn_mma, cudaFuncAttributeMaxDynamicSharedMemorySize, ATM_SMEM);

    dim3 blk(256);

    // [0] x -> hi/lo
    convert_rows<<<4096, blk>>>(x, CCH, (long)MTOT*CCH, CCH, xh, xl);
    // [1][2] weights needed by hgemm<1>
    transpose_convert<<<dim3(2048/32, 2048/32), blk>>>(Wq,   2048, 2048, 0, wqh, wql);
    transpose_convert<<<dim3(2048/32, NAPAD/32), blk>>>(Wkva, CKVW, 2048, 0, wah, wal);

    // [3] merged q-proj + ckv-proj (-> qf fp32, a4 split, ckvf rope cols)
    hgemm<1><<<dim3(21, MTOT/128), blk, HG_SMEM>>>(xh, xl, wqh, wql, nullptr,
        2048, 0, 0);

    // [4][5] remaining weight prep
    transpose_convert<<<dim3(512/32,  1024/32), blk>>>(Wkvb, 1024, 512,  0, wbh, wbl);
    transpose_convert<<<dim3(1024/32, 2048/32), blk>>>(Wo,   2048, 1024, 1, woh, wol);

    // [6] k_rope: rope + broadcast into Kh/Kl cols 64..127
    conv_krope<<<(BB*TT*32 + 255)/256, blk>>>(ckvf, Kh, Kl);

    // [7] kv-up: latent @ Wkvb -> Kh/Kl cols 0..63 (== V)
    hgemm<2><<<dim3(8, MTOT/128), blk, HG_SMEM>>>(a4h, a4l, wbh, wbl, nullptr,
        512, 0, 0);

    // [8] q: rope + hi/lo split -> Qh/Ql
    conv_q<<<8192, blk>>>(qf, Qh, Ql);

    // [9] attention -> a6h/a6l (o-proj operand)
    attn_mma<<<dim3(TT/128, HH, BB), blk, ATM_SMEM>>>(Qh, Ql, Kh, Kl, a6h, a6l);

    // [10] out = y_nope @ Wo[nope rows]
    hgemm<0><<<dim3(16, MTOT/128), blk, HG_SMEM>>>(a6h, a6l, woh, wol, out,
        1024, 2048, 2048);
}

// round 15
// speedup vs baseline: 2.2987x; 1.2921x over previous
#include <cuda_runtime.h>
#include <cuda_fp16.h>
#include <stdint.h>
#include <math.h>
#include <float.h>

// ---------------- problem constants ----------------
#define BB    2
#define TT    2048
#define CCH   2048
#define HH    16
#define HDD   128
#define LORA_ 512
#define RDIM  64
#define NDIM  64
#define MTOT  (BB*TT)        /* 4096 */
#define CKVW  (LORA_+RDIM)   /* 576  */
#define KVW   (HH*NDIM)      /* 1024 */
#define NAPAD 640

// ---------------- fp32 scratch ----------------
__device__ float g_qf  [(size_t)MTOT * 2048];   // q projection (pre-rope)
__device__ float g_ckvf[(size_t)MTOT * CKVW];   // only cols 512..575 used (k_rope)

// ---------------- fp16 buffers ----------------
__device__ __align__(128) __half g_xh [(size_t)MTOT*CCH];
__device__ __align__(128) __half g_wqh[(size_t)2048*2048], g_wql[(size_t)2048*2048];
__device__ __align__(128) __half g_wah[(size_t)NAPAD*2048],g_wal[(size_t)NAPAD*2048];
__device__ __align__(128) __half g_wbh[(size_t)1024*512],  g_wbl[(size_t)1024*512];
__device__ __align__(128) __half g_woh[(size_t)2048*1024], g_wol[(size_t)2048*1024];
__device__ __align__(128) __half g_a4h[(size_t)MTOT*512];
__device__ __align__(128) __half g_a6h[(size_t)MTOT*1024];
// attention operands [bh][t][d]; V == K[:, 0:64]
__device__ __align__(128) __half g_Qh[(size_t)BB*HH*TT*128], g_Ql[(size_t)BB*HH*TT*128];
__device__ __align__(128) __half g_Kh[(size_t)BB*HH*TT*128], g_Kl[(size_t)BB*HH*TT*128];

// =====================================================================
// PTX helpers (baseline sm_80+ — compile at compute_103)
// =====================================================================
__device__ __forceinline__ uint32_t smem_u32(const void* p) {
    uint32_t a;
    asm("{ .reg .u64 t; cvta.to.shared.u64 t, %1; cvt.u32.u64 %0, t; }" : "=r"(a) : "l"(p));
    return a;
}
#define CP_ASYNC16(dst, src) \
    asm volatile("cp.async.cg.shared.global [%0], [%1], 16;" :: "r"(dst), "l"(src))
#define CP_COMMIT() asm volatile("cp.async.commit_group;" ::: "memory")
#define CP_WAIT(n)  asm volatile("cp.async.wait_group %0;" :: "n"(n) : "memory")

#define LDSM4(R, addr) \
    asm volatile("ldmatrix.sync.aligned.m8n8.x4.shared.b16 {%0,%1,%2,%3}, [%4];" \
        : "=r"((R)[0]), "=r"((R)[1]), "=r"((R)[2]), "=r"((R)[3]) : "r"(addr))
#define LDSM4T(R, addr) \
    asm volatile("ldmatrix.sync.aligned.m8n8.x4.trans.shared.b16 {%0,%1,%2,%3}, [%4];" \
        : "=r"((R)[0]), "=r"((R)[1]), "=r"((R)[2]), "=r"((R)[3]) : "r"(addr))

#define MMA16816(D, A, B0, B1) \
    asm volatile("mma.sync.aligned.m16n8k16.row.col.f32.f16.f16.f32 " \
        "{%0,%1,%2,%3}, {%4,%5,%6,%7}, {%8,%9}, {%0,%1,%2,%3};" \
        : "+f"((D)[0]), "+f"((D)[1]), "+f"((D)[2]), "+f"((D)[3]) \
        : "r"((A)[0]), "r"((A)[1]), "r"((A)[2]), "r"((A)[3]), "r"(B0), "r"(B1))

__device__ __forceinline__ uint32_t h2u(__half2 v) { return *(uint32_t*)&v; }

// hi/lo split store of a (v0,v1) pair
__device__ __forceinline__ void sstore2(__half* __restrict__ oh, __half* __restrict__ ol,
                                        size_t idx, float v0, float v1)
{
    __half h0 = __float2half_rn(v0), h1 = __float2half_rn(v1);
    *(__half2*)(oh + idx) = __halves2half2(h0, h1);
    *(__half2*)(ol + idx) = __halves2half2(__float2half_rn(v0 - __half2float(h0)),
                                           __float2half_rn(v1 - __half2float(h1)));
}

// RoPE: freq_i = theta^(-i/32) = 2^(-i*log2(1e5)/32)
#define ROPE_L2F 0.5190512648261504f
__device__ __forceinline__ void rope2(float& v0, float& v1, int t, int i)
{
    float freq = exp2f(-ROPE_L2F * (float)i);
    float sn, cs; sincosf((float)t * freq, &sn, &cs);
    float a = v0*cs - v1*sn;
    float b = v0*sn + v1*cs;
    v0 = a; v1 = b;
}

// =====================================================================
// conversions (prep)
// =====================================================================
// fp32 -> fp16 hi only (for GEMM A operands)
__global__ __launch_bounds__(256)
void convert_hi(const float* __restrict__ in, long total, __half* __restrict__ oh)
{
    long i4 = (long)blockIdx.x * blockDim.x + threadIdx.x;
    long stride = (long)gridDim.x * blockDim.x;
    for (long i = i4*4; i < total; i += stride*4) {
        float4 v = *(const float4*)(in + i);
        *(__half2*)(oh + i)     = __floats2half2_rn(v.x, v.y);
        *(__half2*)(oh + i + 2) = __floats2half2_rn(v.z, v.w);
    }
}

__global__ __launch_bounds__(256)
void transpose_convert(const float* __restrict__ in, int N, int Kdim, int remap,
                       __half* __restrict__ oh, __half* __restrict__ ol)
{
    __shared__ float t[32][33];
    int tx = threadIdx.x & 31, ty = threadIdx.x >> 5;
    int k0 = blockIdx.x * 32, n0 = blockIdx.y * 32;
    #pragma unroll
    for (int i = 0; i < 4; i++) {
        int k = k0 + ty + i*8;
        int kr = remap ? ((k >> 6)*128 + (k & 63)) : k;
        int n = n0 + tx;
        t[ty + i*8][tx] = (n < N) ? in[(size_t)kr*N + n] : 0.f;
    }
    __syncthreads();
    #pragma unroll
    for (int i = 0; i < 4; i++) {
        int n = n0 + ty + i*8;
        int k = k0 + tx;
        float v = t[tx][ty + i*8];
        __half h = __float2half_rn(v);
        size_t o = (size_t)n*Kdim + k;
        oh[o] = h;
        ol[o] = __float2half_rn(v - __half2float(h));
    }
}

// Q: [bh][t][128] <- g_qf[(b*T+t)][h*128+d], rope applied to d>=64
__global__ __launch_bounds__(256)
void conv_q(const float* __restrict__ q, __half* __restrict__ oh, __half* __restrict__ ol)
{
    long i4 = (long)blockIdx.x*blockDim.x + threadIdx.x;
    if (i4 >= (long)BB*HH*TT*32) return;
    long i = i4*4;
    int d = (int)(i & 127); long r = i >> 7;
    int t = (int)(r & (TT-1)); int bh = (int)(r >> 11);
    int hh = bh & 15, bb = bh >> 4;
    float4 v = *(const float4*)&q[((size_t)(bb*TT + t))*2048 + hh*128 + d];
    if (d >= 64) {
        int i0 = (d - 64) >> 1;
        rope2(v.x, v.y, t, i0);
        rope2(v.z, v.w, t, i0 + 1);
    }
    __half h0 = __float2half_rn(v.x), h1 = __float2half_rn(v.y);
    __half h2 = __float2half_rn(v.z), h3 = __float2half_rn(v.w);
    *(__half2*)(oh + i)     = __halves2half2(h0, h1);
    *(__half2*)(oh + i + 2) = __halves2half2(h2, h3);
    *(__half2*)(ol + i)     = __halves2half2(__float2half_rn(v.x - __half2float(h0)),
                                             __float2half_rn(v.y - __half2float(h1)));
    *(__half2*)(ol + i + 2) = __halves2half2(__float2half_rn(v.z - __half2float(h2)),
                                             __float2half_rn(v.w - __half2float(h3)));
}

// k_rope: rope'd ckv cols 512..575 broadcast into Kh/Kl cols 64..127, all heads
__global__ __launch_bounds__(256)
void conv_krope(const float* __restrict__ ckv,
                __half* __restrict__ Kh, __half* __restrict__ Kl)
{
    int idx = blockIdx.x*blockDim.x + threadIdx.x;     // over BB*TT*32
    if (idx >= BB*TT*32) return;
    int i = idx & 31;
    int m = idx >> 5;
    int t = m & (TT-1), b = m >> 11;
    float2 v = *(const float2*)&ckv[(size_t)m*CKVW + LORA_ + 2*i];
    rope2(v.x, v.y, t, i);
    __half h0 = __float2half_rn(v.x), h1 = __float2half_rn(v.y);
    __half2 hi = __halves2half2(h0, h1);
    __half2 lo = __halves2half2(__float2half_rn(v.x - __half2float(h0)),
                                __float2half_rn(v.y - __half2float(h1)));
    size_t base = ((size_t)(b*HH)*TT + t)*128 + 64 + 2*i;
    #pragma unroll
    for (int h = 0; h < HH; h++) {
        *(__half2*)(Kh + base) = hi;
        *(__half2*)(Kl + base) = lo;
        base += (size_t)TT*128;
    }
}

// =====================================================================
// fp16 HMMA GEMM, A plain fp16 + B hi/lo split (2 MMAs per step).
// Stage = {A 8K, Bh 8K, Bl 8K} = 24 KB, 3 stages. 2 CTAs/SM.
// MODE 0: fp32 C (o-proj).
// MODE 1: merged q-proj + ckv-proj. tiles 0..15 -> fp32 g_qf;
//         tiles 16..19 -> fp16 a4h (latent); tile 20 -> fp32 g_ckvf rope.
// MODE 2: kv-up -> hi/lo split into Kh/Kl cols 0..63 (== V).
// =====================================================================
#define STAGE_BYTES 24576
#define HG_STAGES   3
#define HG_SMEM     (STAGE_BYTES*HG_STAGES)   /* 73728 */

template<int MODE>
__global__ __launch_bounds__(256, 2)
void hgemm(const __half* __restrict__ Ah,
           const __half* __restrict__ Bh, const __half* __restrict__ Bl,
           float* __restrict__ C, int K, int ldc, int Nvalid)
{
    extern __shared__ char smem[];
    const uint32_t sb = smem_u32(smem);
    const int tid  = threadIdx.x;
    const int wid  = tid >> 5, lane = tid & 31;
    const int row0 = blockIdx.y * 128;
    const int wm   = wid >> 1;
    const int wn   = wid & 1;

    const __half* BhP = Bh;
    const __half* BlP = Bl;
    int col0 = blockIdx.x * 128;
    if (MODE == 1 && blockIdx.x >= 16) {
        BhP = g_wah; BlP = g_wal;
        col0 = (blockIdx.x - 16) * 128;
    }

    int l_line[2], l_s8[2], l_r[2], l_c[2];
    #pragma unroll
    for (int j = 0; j < 2; j++) {
        int idx = tid + j*256;
        l_line[j] = idx >> 3;
        l_s8[j]   = idx & 7;
        int v     = l_s8[j] ^ (l_line[j] & 7);
        l_r[j]    = l_line[j]*2 + (v >> 2);
        l_c[j]    = v & 3;
    }

#define LOAD_STAGE(CH, ST) do { \
    uint32_t _base = sb + (uint32_t)(ST)*STAGE_BYTES; \
    _Pragma("unroll") \
    for (int _a = 0; _a < 3; _a++) { \
        const __half* _src = (_a == 0) ? Ah : (_a == 1) ? BhP : BlP; \
        int _rb = (_a == 0) ? row0 : col0; \
        _Pragma("unroll") \
        for (int _j = 0; _j < 2; _j++) { \
            const void* _g = _src + (size_t)(_rb + l_r[_j])*(size_t)K \
                             + (CH)*32 + l_c[_j]*8; \
            CP_ASYNC16(_base + _a*8192u + (uint32_t)(l_line[_j]*128 + l_s8[_j]*16), _g); \
        } \
    } \
    CP_COMMIT(); \
} while (0)

    float acc[2][8][4];
    #pragma unroll
    for (int mi = 0; mi < 2; mi++)
        #pragma unroll
        for (int nj = 0; nj < 8; nj++)
            #pragma unroll
            for (int e = 0; e < 4; e++) acc[mi][nj][e] = 0.f;

    const int nch = K >> 5;
    LOAD_STAGE(0, 0);
    LOAD_STAGE(1, 1);

    const int lr8 = (lane & 7) + ((lane >> 3) & 1)*8;
    const int chx = (lane >> 4);

    int st = 0;
    for (int ch = 0; ch < nch; ch++) {
        if (ch + 2 < nch) { CP_WAIT(1); } else { CP_WAIT(0); }
        __syncthreads();
        if (ch + 2 < nch) {
            int st2 = st + 2; if (st2 >= HG_STAGES) st2 -= HG_STAGES;
            LOAD_STAGE(ch + 2, st2);
        }

        const uint32_t base = sb + (uint32_t)st*STAGE_BYTES;
        #pragma unroll
        for (int kk = 0; kk < 2; kk++) {
            const int cc = kk*2 + chx;
            uint32_t a_h[2][4];

            #pragma unroll
            for (int mi = 0; mi < 2; mi++) {
                int r = wm*32 + mi*16 + lr8;
                uint32_t off = (uint32_t)((r >> 1)*128 +
                    (((cc | ((r & 1) << 2)) ^ ((r >> 1) & 7)) << 4));
                LDSM4(a_h[mi], base + off);
            }
            #pragma unroll
            for (int nb = 0; nb < 4; nb++) {
                uint32_t b_h[4], b_l[4];
                int r = wn*64 + nb*16 + lr8;
                uint32_t off = (uint32_t)((r >> 1)*128 +
                    (((cc | ((r & 1) << 2)) ^ ((r >> 1) & 7)) << 4));
                LDSM4(b_h, base + 8192u + off);
                LDSM4(b_l, base + 16384u + off);

                #pragma unroll
                for (int mi = 0; mi < 2; mi++)
                    #pragma unroll
                    for (int nn = 0; nn < 2; nn++) {
                        float* d = acc[mi][nb*2 + nn];
                        MMA16816(d, a_h[mi], b_h[nn], b_h[nn+2]);
                        MMA16816(d, a_h[mi], b_l[nn], b_l[nn+2]);
                    }
            }
        }
        st++; if (st >= HG_STAGES) st = 0;
    }

    // ---- epilogues (trig-free) ----
    #pragma unroll
    for (int mi = 0; mi < 2; mi++) {
        int m = row0 + wm*32 + mi*16 + (lane >> 2);
        #pragma unroll
        for (int nb = 0; nb < 4; nb++)
            #pragma unroll
            for (int nn = 0; nn < 2; nn++) {
                float* d = acc[mi][nb*2 + nn];
                int c = col0 + wn*64 + nb*16 + nn*8 + (lane & 3)*2;

                if (MODE == 0) {
                    if (c < Nvalid) {
                        *(float2*)&C[(size_t)m*ldc + c]       = make_float2(d[0], d[1]);
                        *(float2*)&C[(size_t)(m + 8)*ldc + c] = make_float2(d[2], d[3]);
                    }
                } else if (MODE == 1) {
                    if (blockIdx.x < 16) {
                        *(float2*)&g_qf[(size_t)m*2048 + c]       = make_float2(d[0], d[1]);
                        *(float2*)&g_qf[(size_t)(m + 8)*2048 + c] = make_float2(d[2], d[3]);
                    } else if (c < LORA_) {
                        *(__half2*)(g_a4h + (size_t)m*512 + c)       = __floats2half2_rn(d[0], d[1]);
                        *(__half2*)(g_a4h + (size_t)(m + 8)*512 + c) = __floats2half2_rn(d[2], d[3]);
                    } else if (c < CKVW) {
                        *(float2*)&g_ckvf[(size_t)m*CKVW + c]       = make_float2(d[0], d[1]);
                        *(float2*)&g_ckvf[(size_t)(m + 8)*CKVW + c] = make_float2(d[2], d[3]);
                    }
                } else { // MODE 2: kv-up -> Kh/Kl nope cols (K needs hi AND lo for S)
                    int tA = m & (TT-1), bbA = m >> 11;
                    int h = c >> 6, dd = c & 63;
                    size_t b0 = ((size_t)(bbA*HH + h)*TT + tA)*128 + dd;
                    sstore2(g_Kh, g_Kl, b0, d[0], d[1]);
                    sstore2(g_Kh, g_Kl, b0 + (size_t)8*128, d[2], d[3]);
                }
            }
    }
}

// =====================================================================
// HMMA causal flash attention. V read from K tile (cols 0..63),
// PV uses V-hi only; epilogue writes Oh only (o-proj A operand).
// smem: Qh/Ql 64K + 2 stages {Kh 16K, Kl 16K}.
// =====================================================================
#define ATM_SCALE 0.08838834764831845f
#define ATM_STAGE 32768
#define ATM_SMEM  (65536 + 2*ATM_STAGE)   /* 131072 */

__global__ __launch_bounds__(256, 1)
void attn_mma(const __half* __restrict__ Qh, const __half* __restrict__ Ql,
              const __half* __restrict__ Kh, const __half* __restrict__ Kl,
              __half* __restrict__ Oh)
{
    extern __shared__ char smem[];
    const uint32_t sb = smem_u32(smem);
    const int tid  = threadIdx.x;
    const int wm   = tid >> 5, lane = tid & 31;
    const int qt   = (int)gridDim.x - 1 - (int)blockIdx.x;
    const int h    = blockIdx.y, b = blockIdx.z;
    const int bh   = b*HH + h;
    const int t0   = qt * 128;
    const size_t qrow  = ((size_t)bh*TT + t0)*128;
    const size_t krow0 = (size_t)bh*TT*128;

    for (int i = tid; i < 2048; i += 256) {
        int r = i >> 4, s = i & 15;
        uint32_t ph = (uint32_t)(r*256 + ((s ^ (r & 7)) << 4));
        *(uint4*)(smem + ph)         = *(const uint4*)(Qh + qrow + (size_t)r*128 + s*8);
        *(uint4*)(smem + 32768 + ph) = *(const uint4*)(Ql + qrow + (size_t)r*128 + s*8);
    }

    const int lr8 = (lane & 7) + ((lane >> 3) & 1)*8;
    const int chx = lane >> 4;

    float o_acc[8][4];
    #pragma unroll
    for (int j = 0; j < 8; j++)
        #pragma unroll
        for (int e = 0; e < 4; e++) o_acc[j][e] = 0.f;
    float m0 = -1e30f, m1 = -1e30f, l0 = 0.f, l1 = 0.f;

    const int nkt = 2*qt + 2;

#define ATM_PRE(KT, ST) do { \
    uint32_t bs = sb + 65536 + (uint32_t)(ST)*ATM_STAGE; \
    const __half* kh_ = Kh + krow0 + (size_t)(KT)*64*128; \
    const __half* kl_ = Kl + krow0 + (size_t)(KT)*64*128; \
    for (int i = tid; i < 1024; i += 256) { \
        int r = i >> 4, s = i & 15; \
        uint32_t ph = (uint32_t)(r*256 + ((s ^ (r & 7)) << 4)); \
        CP_ASYNC16(bs + ph,         kh_ + (size_t)r*128 + s*8); \
        CP_ASYNC16(bs + 16384 + ph, kl_ + (size_t)r*128 + s*8); \
    } \
    CP_COMMIT(); \
} while (0)

    ATM_PRE(0, 0);

    for (int kt = 0; kt < nkt; kt++) {
        const int st = kt & 1;
        CP_WAIT(0);
        __syncthreads();
        if (kt + 1 < nkt) ATM_PRE(kt + 1, st ^ 1);

        const uint32_t ks = sb + 65536 + (uint32_t)st*ATM_STAGE;

        float sacc[8][4];
        #pragma unroll
        for (int j = 0; j < 8; j++)
            #pragma unroll
            for (int e = 0; e < 4; e++) sacc[j][e] = 0.f;

        #pragma unroll
        for (int cc = 0; cc < 8; cc++) {
            uint32_t aqh[4], aql[4];
            {
                int r = wm*16 + lr8;
                int s = cc*2 + chx;
                uint32_t off = (uint32_t)(r*256 + ((s ^ (r & 7)) << 4));
                LDSM4(aqh, sb + off);
                LDSM4(aql, sb + 32768u + off);
            }
            #pragma unroll
            for (int nb = 0; nb < 4; nb++) {
                uint32_t bkh[4], bkl[4];
                int rn = nb*16 + lr8;
                int s = cc*2 + chx;
                uint32_t off = (uint32_t)(rn*256 + ((s ^ (rn & 7)) << 4));
                LDSM4(bkh, ks + off);
                LDSM4(bkl, ks + 16384u + off);
                MMA16816(sacc[nb*2],     aqh, bkh[0], bkh[2]);
                MMA16816(sacc[nb*2],     aqh, bkl[0], bkl[2]);
                MMA16816(sacc[nb*2],     aql, bkh[0], bkh[2]);
                MMA16816(sacc[nb*2 + 1], aqh, bkh[1], bkh[3]);
                MMA16816(sacc[nb*2 + 1], aqh, bkl[1], bkl[3]);
                MMA16816(sacc[nb*2 + 1], aql, bkh[1], bkh[3]);
            }
        }

        if (kt >= 2*qt) {
            int s0 = kt*64;
            int rb = t0 + wm*16 + (lane >> 2);
            #pragma unroll
            for (int j = 0; j < 8; j++) {
                int c0 = s0 + j*8 + (lane & 3)*2;
                if (c0     > rb)     sacc[j][0] = -3.0e38f;
                if (c0 + 1 > rb)     sacc[j][1] = -3.0e38f;
                if (c0     > rb + 8) sacc[j][2] = -3.0e38f;
                if (c0 + 1 > rb + 8) sacc[j][3] = -3.0e38f;
            }
        }

        float rm0 = -3.0e38f, rm1 = -3.0e38f;
        #pragma unroll
        for (int j = 0; j < 8; j++) {
            rm0 = fmaxf(rm0, fmaxf(sacc[j][0], sacc[j][1]));
            rm1 = fmaxf(rm1, fmaxf(sacc[j][2], sacc[j][3]));
        }
        rm0 = fmaxf(rm0, __shfl_xor_sync(0xffffffffu, rm0, 1));
        rm0 = fmaxf(rm0, __shfl_xor_sync(0xffffffffu, rm0, 2));
        rm1 = fmaxf(rm1, __shfl_xor_sync(0xffffffffu, rm1, 1));
        rm1 = fmaxf(rm1, __shfl_xor_sync(0xffffffffu, rm1, 2));
        float mn0 = fmaxf(m0, rm0), mn1 = fmaxf(m1, rm1);
        float f0  = __expf(ATM_SCALE*(m0 - mn0));
        float f1  = __expf(ATM_SCALE*(m1 - mn1));
        m0 = mn0; m1 = mn1;
        float rs0 = 0.f, rs1 = 0.f;
        #pragma unroll
        for (int j = 0; j < 8; j++) {
            sacc[j][0] = __expf(ATM_SCALE*(sacc[j][0] - mn0)); rs0 += sacc[j][0];
            sacc[j][1] = __expf(ATM_SCALE*(sacc[j][1] - mn0)); rs0 += sacc[j][1];
            sacc[j][2] = __expf(ATM_SCALE*(sacc[j][2] - mn1)); rs1 += sacc[j][2];
            sacc[j][3] = __expf(ATM_SCALE*(sacc[j][3] - mn1)); rs1 += sacc[j][3];
        }
        rs0 += __shfl_xor_sync(0xffffffffu, rs0, 1);
        rs0 += __shfl_xor_sync(0xffffffffu, rs0, 2);
        rs1 += __shfl_xor_sync(0xffffffffu, rs1, 1);
        rs1 += __shfl_xor_sync(0xffffffffu, rs1, 2);
        l0 = l0*f0 + rs0; l1 = l1*f1 + rs1;
        #pragma unroll
        for (int j = 0; j < 8; j++) {
            o_acc[j][0] *= f0; o_acc[j][1] *= f0;
            o_acc[j][2] *= f1; o_acc[j][3] *= f1;
        }

        uint32_t pf[4][4];
        #pragma unroll
        for (int kk = 0; kk < 4; kk++) {
            pf[kk][0] = h2u(__floats2half2_rn(sacc[2*kk][0],     sacc[2*kk][1]));
            pf[kk][1] = h2u(__floats2half2_rn(sacc[2*kk][2],     sacc[2*kk][3]));
            pf[kk][2] = h2u(__floats2half2_rn(sacc[2*kk + 1][0], sacc[2*kk + 1][1]));
            pf[kk][3] = h2u(__floats2half2_rn(sacc[2*kk + 1][2], sacc[2*kk + 1][3]));
        }

        // ---- O += P V  (V = K-hi cols 0..63 only) ----
        #pragma unroll
        for (int kk = 0; kk < 4; kk++) {
            #pragma unroll
            for (int nb = 0; nb < 4; nb++) {
                uint32_t bvh[4];
                int rv = kk*16 + lr8;
                int s = nb*2 + chx;
                uint32_t off = (uint32_t)(rv*256 + ((s ^ (rv & 7)) << 4));
                LDSM4T(bvh, ks + off);
                MMA16816(o_acc[nb*2],     pf[kk], bvh[0], bvh[1]);
                MMA16816(o_acc[nb*2 + 1], pf[kk], bvh[2], bvh[3]);
            }
        }
    }

    float il0 = 1.0f/l0, il1 = 1.0f/l1;
    int r0g = b*TT + t0 + wm*16 + (lane >> 2);
    size_t ob0 = (size_t)r0g*KVW + h*64;
    size_t ob1 = ob0 + (size_t)8*KVW;
    #pragma unroll
    for (int j = 0; j < 8; j++) {
        int d = j*8 + (lane & 3)*2;
        *(__half2*)(Oh + ob0 + d) = __floats2half2_rn(o_acc[j][0]*il0, o_acc[j][1]*il0);
        *(__half2*)(Oh + ob1 + d) = __floats2half2_rn(o_acc[j][2]*il1, o_acc[j][3]*il1);
    }
}

// =====================================================================
// launch  (hgemm<1> at our index 3 for ncu capture)
// =====================================================================
extern "C" void kernel_launch(void* const* d_in, const int* in_sizes, int n_in,
                              void* d_out, int out_size)
{
    const float* x    = (const float*)d_in[0];
    const float* Wq   = (const float*)d_in[1];
    const float* Wkva = (const float*)d_in[2];
    const float* Wkvb = (const float*)d_in[3];
    const float* Wo   = (const float*)d_in[4];
    float* out        = (float*)d_out;

    float *qf, *ckvf;
    cudaGetSymbolAddress((void**)&qf,   g_qf);
    cudaGetSymbolAddress((void**)&ckvf, g_ckvf);

    __half *xh,*wqh,*wql,*wah,*wal,*wbh,*wbl,*woh,*wol,*a4h,*a6h;
    __half *Qh,*Ql,*Kh,*Kl;
    cudaGetSymbolAddress((void**)&xh,  g_xh);
    cudaGetSymbolAddress((void**)&wqh, g_wqh); cudaGetSymbolAddress((void**)&wql, g_wql);
    cudaGetSymbolAddress((void**)&wah, g_wah); cudaGetSymbolAddress((void**)&wal, g_wal);
    cudaGetSymbolAddress((void**)&wbh, g_wbh); cudaGetSymbolAddress((void**)&wbl, g_wbl);
    cudaGetSymbolAddress((void**)&woh, g_woh); cudaGetSymbolAddress((void**)&wol, g_wol);
    cudaGetSymbolAddress((void**)&a4h, g_a4h);
    cudaGetSymbolAddress((void**)&a6h, g_a6h);
    cudaGetSymbolAddress((void**)&Qh,  g_Qh);  cudaGetSymbolAddress((void**)&Ql,  g_Ql);
    cudaGetSymbolAddress((void**)&Kh,  g_Kh);  cudaGetSymbolAddress((void**)&Kl,  g_Kl);

    cudaFuncSetAttribute(hgemm<0>, cudaFuncAttributeMaxDynamicSharedMemorySize, HG_SMEM);
    cudaFuncSetAttribute(hgemm<1>, cudaFuncAttributeMaxDynamicSharedMemorySize, HG_SMEM);
    cudaFuncSetAttribute(hgemm<2>, cudaFuncAttributeMaxDynamicSharedMemorySize, HG_SMEM);
    cudaFuncSetAttribute(attn_mma, cudaFuncAttributeMaxDynamicSharedMemorySize, ATM_SMEM);

    dim3 blk(256);

    // [0] x -> fp16 hi
    convert_hi<<<2048, blk>>>(x, (long)MTOT*CCH, xh);
    // [1][2] weights needed by hgemm<1>
    transpose_convert<<<dim3(2048/32, 2048/32), blk>>>(Wq,   2048, 2048, 0, wqh, wql);
    transpose_convert<<<dim3(2048/32, NAPAD/32), blk>>>(Wkva, CKVW, 2048, 0, wah, wal);

    // [3] merged q-proj + ckv-proj (-> qf fp32, a4h fp16, ckvf rope cols)
    hgemm<1><<<dim3(21, MTOT/128), blk, HG_SMEM>>>(xh, wqh, wql, nullptr,
        2048, 0, 0);

    // [4][5] remaining weight prep
    transpose_convert<<<dim3(512/32,  1024/32), blk>>>(Wkvb, 1024, 512,  0, wbh, wbl);
    transpose_convert<<<dim3(1024/32, 2048/32), blk>>>(Wo,   2048, 1024, 1, woh, wol);

    // [6] k_rope: rope + broadcast into Kh/Kl cols 64..127
    conv_krope<<<(BB*TT*32 + 255)/256, blk>>>(ckvf, Kh, Kl);

    // [7] kv-up: latent @ Wkvb -> Kh/Kl cols 0..63 (== V)
    hgemm<2><<<dim3(8, MTOT/128), blk, HG_SMEM>>>(a4h, wbh, wbl, nullptr,
        512, 0, 0);

    // [8] q: rope + hi/lo split -> Qh/Ql
    conv_q<<<8192, blk>>>(qf, Qh, Ql);

    // [9] attention -> a6h (o-proj operand)
    attn_mma<<<dim3(TT/128, HH, BB), blk, ATM_SMEM>>>(Qh, Ql, Kh, Kl, a6h);

    // [10] out = y_nope @ Wo[nope rows]
    hgemm<0><<<dim3(16, MTOT/128), blk, HG_SMEM>>>(a6h, woh, wol, out,
        1024, 2048, 2048);
}